// round 11
// baseline (speedup 1.0000x reference)
#include <cuda_runtime.h>
#include <cuda_bf16.h>
#include <mma.h>
#include <math.h>

using namespace nvcuda;

#define NN_ 2048
#define BB_ 8

typedef unsigned long long ull;

__device__ __forceinline__ ull pk2(float x, float y) {
    ull r; asm("mov.b64 %0,{%1,%2};" : "=l"(r) : "f"(x), "f"(y)); return r;
}
__device__ __forceinline__ ull dup2(float x) { return pk2(x, x); }
__device__ __forceinline__ void fma2(ull& d, ull a, ull b) {
    asm("fma.rn.f32x2 %0,%1,%2,%0;" : "+l"(d) : "l"(a), "l"(b));
}
__device__ __forceinline__ float2 unpk2(ull v) {
    float2 f; asm("mov.b64 {%0,%1},%2;" : "=f"(f.x), "=f"(f.y) : "l"(v)); return f;
}
__device__ __forceinline__ void lds128(ull& a, ull& b, const float* p) {
    unsigned addr = (unsigned)__cvta_generic_to_shared((void*)p);
    asm("ld.shared.v2.b64 {%0,%1},[%2];" : "=l"(a), "=l"(b) : "r"(addr));
}
__device__ __forceinline__ float wred(float v) {
#pragma unroll
    for (int o = 16; o; o >>= 1) v += __shfl_xor_sync(0xFFFFFFFFu, v, o);
    return v;
}

// ---------------- scratch ----------------
__device__ float g_xT[4194304];      // [B,4,N,C]
__device__ float g_feat[16777216];   // node-major [n][b][t][128]
__device__ float g_el[262144];       // [b,t,n,2]
__device__ float g_er[262144];
__device__ float g_alpha[1310720];   // [e][b][2*TIN]
__device__ float g_y[16777216];      // [b,8,n,64]
__device__ float g_z[16777216];      // [b,16,n,64]
__device__ float g_o1[12582912];     // [b,12,n,64]
__device__ float g_o2[12582912];
__device__ float g_wtm[20480];       // conv1 weights [k*64+ci][co]
__device__ float g_wp1[8192];        // W1 packed [k][lane32][4] (gemm1)
__device__ float g_wtm2[4096];       // tc2 weights [ci][co]
__device__ double g_stat[1024];
__device__ int   g_deg[2048];
__device__ int   g_cursor[2048];
__device__ int   g_rowptr[2049];
__device__ int   g_col[16384];

// ---------------- transpose x (+ zero deg) ----------------
__global__ void k_transpose_x(const float* __restrict__ x, float* __restrict__ xT,
                              int* __restrict__ deg) {
    int i = blockIdx.x * 256 + threadIdx.x;
    if (i < 2048) deg[i] = 0;
    if (i >= BB_ * NN_ * 4 * 64) return;
    int c = i & 63;
    int t = (i >> 6) & 3;
    int n = (i >> 8) & 2047;
    int b = i >> 19;
    xT[((size_t)(b * 4 + t) * 2048 + n) * 64 + c] = x[i];
}

// ---------------- CSR build ----------------
__global__ void k_count(const int* __restrict__ dst, int* __restrict__ deg, int E) {
    int e = blockIdx.x * 256 + threadIdx.x;
    if (e < E) atomicAdd(&deg[dst[e]], 1);
}

__global__ void k_scan(const int* __restrict__ deg, int* __restrict__ rowptr,
                       int* __restrict__ cursor) {
    __shared__ int s[2048];
    int tid = threadIdx.x;
    s[tid] = deg[tid];
    s[tid + 1024] = deg[tid + 1024];
    __syncthreads();
    for (int off = 1; off < 2048; off <<= 1) {
        int i0 = tid, i1 = tid + 1024;
        int a0 = (i0 >= off) ? s[i0 - off] : 0;
        int a1 = (i1 >= off) ? s[i1 - off] : 0;
        __syncthreads();
        s[i0] += a0; s[i1] += a1;
        __syncthreads();
    }
    rowptr[tid + 1] = s[tid];
    rowptr[tid + 1025] = s[tid + 1024];
    if (tid == 0) { rowptr[0] = 0; cursor[0] = 0; }
    if (tid < 1023) cursor[tid + 1] = s[tid];
    cursor[tid + 1024] = s[tid + 1023];
}

__global__ void k_fill_atomic(const int* __restrict__ dst, const int* __restrict__ src,
                              int* __restrict__ cursor, int* __restrict__ col, int E) {
    int e = blockIdx.x * 256 + threadIdx.x;
    if (e >= E) return;
    int pos = atomicAdd(&cursor[dst[e]], 1);
    col[pos] = src[e];
}

__global__ void k_sortcol(const int* __restrict__ rowptr, int* __restrict__ col) {
    int n = blockIdx.x * 256 + threadIdx.x;
    if (n >= NN_) return;
    int r0 = rowptr[n], r1 = rowptr[n + 1];
    for (int i = r0 + 1; i < r1; i++) {
        int v = col[i];
        int j = i - 1;
        while (j >= r0 && col[j] > v) { col[j + 1] = col[j]; j--; }
        col[j + 1] = v;
    }
}

// ---------------- weight prep ----------------
// tc1w [co][ci][5] -> wtm [k*64+ci][co]
__global__ void k_twm(const float* __restrict__ w, float* __restrict__ wtm) {
    int i = blockIdx.x * 256 + threadIdx.x;
    if (i >= 20480) return;
    int co = i & 63;
    int ci = (i >> 6) & 63;
    int k = i >> 12;
    wtm[(k * 64 + ci) * 64 + co] = w[(co * 64 + ci) * 5 + k];
}

// tc2w [co][ci] -> wtm2 [ci][co]
__global__ void k_tw2(const float* __restrict__ w, float* __restrict__ wt) {
    int i = blockIdx.x * 256 + threadIdx.x;
    if (i >= 4096) return;
    int ci = i >> 6, co = i & 63;
    wt[i] = w[co * 64 + ci];
}

__global__ void k_packw128(const float* __restrict__ w, float* __restrict__ wp) {
    int i = blockIdx.x * 256 + threadIdx.x;
    if (i >= 8192) return;
    int k = i >> 7, rem = i & 127, j = rem >> 5, lane = rem & 31;
    wp[(k * 32 + lane) * 4 + j] = w[i];
}

// ---------------- LN partial stats ----------------
__global__ void k_lnpart(const float* __restrict__ x, double* __restrict__ stat) {
    int slice = blockIdx.x >> 2, q = blockIdx.x & 3;
    const float* xs = x + (size_t)slice * 131072 + q * 32768;
    double s1 = 0.0, s2 = 0.0;
    for (int i = threadIdx.x; i < 32768; i += 1024) {
        float v = xs[i];
        s1 += v;
        s2 += (double)v * (double)v;
    }
    for (int o = 16; o; o >>= 1) {
        s1 += __shfl_xor_sync(0xFFFFFFFFu, s1, o);
        s2 += __shfl_xor_sync(0xFFFFFFFFu, s2, o);
    }
    __shared__ double sh1[32], sh2[32];
    int wid = threadIdx.x >> 5, lane = threadIdx.x & 31;
    if (!lane) { sh1[wid] = s1; sh2[wid] = s2; }
    __syncthreads();
    if (threadIdx.x == 0) {
        double t1 = 0, t2 = 0;
        for (int k = 0; k < 32; k++) { t1 += sh1[k]; t2 += sh2[k]; }
        stat[slice * 8 + q * 2] = t1;
        stat[slice * 8 + q * 2 + 1] = t2;
    }
}

__device__ __forceinline__ void ln_combine(const double* __restrict__ stat, int slice,
                                           float& mu, float& rs) {
    double t1 = 0, t2 = 0;
#pragma unroll
    for (int q = 0; q < 4; q++) {
        t1 += stat[slice * 8 + q * 2];
        t2 += stat[slice * 8 + q * 2 + 1];
    }
    double m = t1 / 131072.0;
    double var = t2 / 131072.0 - m * m;
    mu = (float)m;
    rs = (float)rsqrt(var + 1e-5);
}

// split-tf32 helpers
template <typename Frag>
__device__ __forceinline__ void split_frag(const Frag& f, Frag& hi, Frag& lo) {
#pragma unroll
    for (int t = 0; t < f.num_elements; t++) {
        float v = f.x[t];
        float h = wmma::__float_to_tf32(v);
        hi.x[t] = h;
        lo.x[t] = wmma::__float_to_tf32(v - h);
    }
}

// ---------------- gemm1: warp-tiled f32x2 (fp32 exact, ELR epilogue) ----------------
template <int TIN>
__global__ __launch_bounds__(256, 3) void k_gemm1(
        const float* __restrict__ in, const float* __restrict__ wp,
        float* __restrict__ out, const float* __restrict__ al, const float* __restrict__ ar,
        float* __restrict__ el, float* __restrict__ er) {
    size_t m0 = (size_t)blockIdx.x * 64;
    int tid = threadIdx.x;
    int warp = tid >> 5, lane = tid & 31;
    __shared__ __align__(16) float xs[64 * 64];
    for (int i = tid; i < 64 * 64; i += 256) {
        int r = i >> 6, k = i & 63;
        xs[k * 64 + r] = in[m0 * 64 + i];
    }
    __syncthreads();
    int rbase = warp * 8;
    ull acc[4][4];
#pragma unroll
    for (int p = 0; p < 4; p++)
#pragma unroll
        for (int j = 0; j < 4; j++) acc[p][j] = 0ull;
#pragma unroll 8
    for (int k = 0; k < 64; k++) {
        ull xv[4];
        const float* xp = &xs[k * 64 + rbase];
        lds128(xv[0], xv[1], xp);
        lds128(xv[2], xv[3], xp + 4);
        float4 w4 = *(const float4*)&wp[(k * 32 + lane) * 4];
        ull wd[4] = {dup2(w4.x), dup2(w4.y), dup2(w4.z), dup2(w4.w)};
#pragma unroll
        for (int p = 0; p < 4; p++)
#pragma unroll
            for (int j = 0; j < 4; j++) fma2(acc[p][j], xv[p], wd[j]);
    }
    const size_t rowstride = (size_t)8 * TIN * 128;
    size_t base = (size_t)(m0 & 2047) * rowstride + (size_t)(m0 >> 11) * 128;
    float al0 = al[lane], al1 = al[lane + 32], al2v = al[lane + 64], al3 = al[lane + 96];
    float ar0 = ar[lane], ar1 = ar[lane + 32], ar2v = ar[lane + 64], ar3 = ar[lane + 96];
#pragma unroll
    for (int p = 0; p < 4; p++) {
        float2 v0 = unpk2(acc[p][0]);
        float2 v1 = unpk2(acc[p][1]);
        float2 v2 = unpk2(acc[p][2]);
        float2 v3 = unpk2(acc[p][3]);
        size_t a0 = base + (size_t)(rbase + 2 * p) * rowstride;
        size_t a1 = a0 + rowstride;
        out[a0 + lane] = v0.x; out[a0 + lane + 32] = v1.x;
        out[a0 + lane + 64] = v2.x; out[a0 + lane + 96] = v3.x;
        out[a1 + lane] = v0.y; out[a1 + lane + 32] = v1.y;
        out[a1 + lane + 64] = v2.y; out[a1 + lane + 96] = v3.y;
        float sl0x = wred(v0.x * al0 + v1.x * al1);
        float sl1x = wred(v2.x * al2v + v3.x * al3);
        float sr0x = wred(v0.x * ar0 + v1.x * ar1);
        float sr1x = wred(v2.x * ar2v + v3.x * ar3);
        float sl0y = wred(v0.y * al0 + v1.y * al1);
        float sl1y = wred(v2.y * al2v + v3.y * al3);
        float sr0y = wred(v0.y * ar0 + v1.y * ar1);
        float sr1y = wred(v2.y * ar2v + v3.y * ar3);
        if (lane == 0) {
            size_t rA = m0 + rbase + 2 * p;
            el[rA * 2 + 0] = sl0x; el[rA * 2 + 1] = sl1x;
            er[rA * 2 + 0] = sr0x; er[rA * 2 + 1] = sr1x;
            el[(rA + 1) * 2 + 0] = sl0y; el[(rA + 1) * 2 + 1] = sl1y;
            er[(rA + 1) * 2 + 0] = sr0y; er[(rA + 1) * 2 + 1] = sr1y;
        }
    }
}

// ---------------- gemm2: split-tf32 wmma, LN1 fused, writes feat node-major ----------------
// C[128 x 128] per block; warp w owns rows [w*16, w*16+16) x all 8 n-tiles.
__global__ __launch_bounds__(256) void k_wgemm2(
        const float* __restrict__ in, const float* __restrict__ W,
        float* __restrict__ feat,
        const float* __restrict__ lnw, const float* __restrict__ lnb,
        const double* __restrict__ stat) {
    const int TIN = 8;
    size_t m0 = (size_t)blockIdx.x * 128;
    int tid = threadIdx.x;
    int w = tid >> 5;
    __shared__ __align__(16) float abuf[128 * 72];
    __shared__ float mu_s, rs_s;
    if (tid == 0) ln_combine(stat, (int)(m0 >> 11), mu_s, rs_s);
    __syncthreads();
    float mu = mu_s, rs = rs_s;
    for (int i = tid; i < 128 * 64; i += 256) {
        int r = i >> 6, k = i & 63;
        int n = (int)((m0 + r) & 2047);
        float v = in[m0 * 64 + i];
        abuf[r * 72 + k] = (v - mu) * rs * lnw[n * 64 + k] + lnb[n * 64 + k];
    }
    __syncthreads();
    wmma::fragment<wmma::accumulator, 16, 16, 8, float> cf[8];
#pragma unroll
    for (int i = 0; i < 8; i++) wmma::fill_fragment(cf[i], 0.f);
#pragma unroll
    for (int kk = 0; kk < 8; kk++) {
        wmma::fragment<wmma::matrix_a, 16, 16, 8, wmma::precision::tf32, wmma::row_major> af, ah, al_;
        wmma::load_matrix_sync(af, abuf + (w * 16) * 72 + kk * 8, 72);
        split_frag(af, ah, al_);
#pragma unroll
        for (int nt = 0; nt < 8; nt++) {
            wmma::fragment<wmma::matrix_b, 16, 16, 8, wmma::precision::tf32, wmma::row_major> bf, bh, bl;
            wmma::load_matrix_sync(bf, W + (size_t)(kk * 8) * 128 + nt * 16, 128);
            split_frag(bf, bh, bl);
            wmma::mma_sync(cf[nt], ah, bh, cf[nt]);
            wmma::mma_sync(cf[nt], ah, bl, cf[nt]);
            wmma::mma_sync(cf[nt], al_, bh, cf[nt]);
        }
    }
    // store to feat: row m = m0 + w*16 + rr ; addr = n*8192 + bt*128 + c
    const size_t rowstride = (size_t)8 * TIN * 128;  // 8192
    size_t base = (size_t)((m0 & 2047) + w * 16) * rowstride + (size_t)(m0 >> 11) * 128;
#pragma unroll
    for (int nt = 0; nt < 8; nt++)
        wmma::store_matrix_sync(feat + base + nt * 16, cf[nt], rowstride, wmma::mem_row_major);
}

// ---------------- el/er from feat (TIN=8): one warp per row ----------------
__global__ void k_elr2(const float* __restrict__ feat, const float* __restrict__ al,
                       const float* __restrict__ ar, float* __restrict__ el,
                       float* __restrict__ er) {
    int r = blockIdx.x * 8 + (threadIdx.x >> 5);
    int lane = threadIdx.x & 31;
    int n = r & 2047, bt = r >> 11;
    const float* f = feat + (size_t)n * 8192 + bt * 128;
    float f0 = f[lane], f1 = f[lane + 32], f2 = f[lane + 64], f3 = f[lane + 96];
    float e0 = wred(f0 * al[lane] + f1 * al[lane + 32]);
    float e1 = wred(f2 * al[lane + 64] + f3 * al[lane + 96]);
    float r0 = wred(f0 * ar[lane] + f1 * ar[lane + 32]);
    float r1 = wred(f2 * ar[lane + 64] + f3 * ar[lane + 96]);
    if (lane == 0) {
        el[(size_t)r * 2 + 0] = e0; el[(size_t)r * 2 + 1] = e1;
        er[(size_t)r * 2 + 0] = r0; er[(size_t)r * 2 + 1] = r1;
    }
}

// ---------------- gemm3: split-tf32 wmma, LN3 fused, o1 -> o2 (bias deferred to fc) ----------------
__global__ __launch_bounds__(256) void k_wgemm3(
        const float* __restrict__ in, const float* __restrict__ W,
        float* __restrict__ out,
        const float* __restrict__ lnw, const float* __restrict__ lnb,
        const double* __restrict__ stat) {
    size_t m0 = (size_t)blockIdx.x * 128;
    int tid = threadIdx.x;
    int w = tid >> 5;
    __shared__ __align__(16) float abuf[128 * 72];
    __shared__ float mu_s, rs_s;
    if (tid == 0) ln_combine(stat, (int)(m0 >> 11), mu_s, rs_s);
    __syncthreads();
    float mu = mu_s, rs = rs_s;
    for (int i = tid; i < 128 * 64; i += 256) {
        int r = i >> 6, k = i & 63;
        int n = (int)((m0 + r) & 2047);
        float v = in[m0 * 64 + i];
        abuf[r * 72 + k] = (v - mu) * rs * lnw[n * 64 + k] + lnb[n * 64 + k];
    }
    __syncthreads();
    wmma::fragment<wmma::accumulator, 16, 16, 8, float> cf[4];
#pragma unroll
    for (int i = 0; i < 4; i++) wmma::fill_fragment(cf[i], 0.f);
#pragma unroll
    for (int kk = 0; kk < 8; kk++) {
        wmma::fragment<wmma::matrix_a, 16, 16, 8, wmma::precision::tf32, wmma::row_major> af, ah, al_;
        wmma::load_matrix_sync(af, abuf + (w * 16) * 72 + kk * 8, 72);
        split_frag(af, ah, al_);
#pragma unroll
        for (int nt = 0; nt < 4; nt++) {
            wmma::fragment<wmma::matrix_b, 16, 16, 8, wmma::precision::tf32, wmma::row_major> bf, bh, bl;
            wmma::load_matrix_sync(bf, W + (size_t)(kk * 8) * 64 + nt * 16, 64);
            split_frag(bf, bh, bl);
            wmma::mma_sync(cf[nt], ah, bh, cf[nt]);
            wmma::mma_sync(cf[nt], ah, bl, cf[nt]);
            wmma::mma_sync(cf[nt], al_, bh, cf[nt]);
        }
    }
#pragma unroll
    for (int nt = 0; nt < 4; nt++)
        wmma::store_matrix_sync(out + (m0 + w * 16) * 64 + nt * 16, cf[nt], 64, wmma::mem_row_major);
}

// ---------------- edge softmax alpha: [e][b][2*TIN] ----------------
template <int TIN>
__global__ void k_alpha(const float* __restrict__ el, const float* __restrict__ er,
                        const int* __restrict__ rowptr, const int* __restrict__ col,
                        float* __restrict__ alpha) {
    const int STR = 2 * TIN;
    int gw = blockIdx.x * 8 + (threadIdx.x >> 5);
    int n = gw >> 3, b = gw & 7;
    int lane = threadIdx.x & 31;
    int r0 = rowptr[n], deg = rowptr[n + 1] - r0;
    const float2* el2 = (const float2*)el;
    const float2* er2 = (const float2*)er;
    if (deg <= 32) {
        int s = (lane < deg) ? col[r0 + lane] : 0;
        float av[STR];
        for (int t = 0; t < TIN; t++) {
            int base = (b * TIN + t) * 2048;
            float2 erd = er2[base + n];
            float2 ela = (lane < deg) ? el2[base + s] : make_float2(-3.0e38f, -3.0e38f);
#pragma unroll
            for (int h = 0; h < 2; h++) {
                float v = (h ? ela.y + erd.y : ela.x + erd.x);
                float e = (lane < deg) ? (v > 0.f ? v : 0.2f * v) : -3.0e38f;
                float mx = e;
                for (int o = 16; o; o >>= 1) mx = fmaxf(mx, __shfl_xor_sync(0xFFFFFFFFu, mx, o));
                float a = (lane < deg) ? __expf(e - mx) : 0.f;
                float sm = a;
                for (int o = 16; o; o >>= 1) sm += __shfl_xor_sync(0xFFFFFFFFu, sm, o);
                av[t * 2 + h] = a / sm;
            }
        }
        if (lane < deg) {
            float4* ap = (float4*)&alpha[((size_t)(r0 + lane) * 8 + b) * STR];
#pragma unroll
            for (int q = 0; q < STR / 4; q++) ap[q] = ((float4*)av)[q];
        }
    } else {
        for (int t = 0; t < TIN; t++) {
            int base = (b * TIN + t) * 2048;
            for (int h = 0; h < 2; h++) {
                float erd = er[(size_t)(base + n) * 2 + h];
                float mx = -3.0e38f;
                for (int j = lane; j < deg; j += 32) {
                    float v = el[(size_t)(base + col[r0 + j]) * 2 + h] + erd;
                    v = v > 0.f ? v : 0.2f * v;
                    mx = fmaxf(mx, v);
                }
                for (int o = 16; o; o >>= 1) mx = fmaxf(mx, __shfl_xor_sync(0xFFFFFFFFu, mx, o));
                float sm = 0.f;
                for (int j = lane; j < deg; j += 32) {
                    float v = el[(size_t)(base + col[r0 + j]) * 2 + h] + erd;
                    v = v > 0.f ? v : 0.2f * v;
                    sm += __expf(v - mx);
                }
                for (int o = 16; o; o >>= 1) sm += __shfl_xor_sync(0xFFFFFFFFu, sm, o);
                for (int j = lane; j < deg; j += 32) {
                    float v = el[(size_t)(base + col[r0 + j]) * 2 + h] + erd;
                    v = v > 0.f ? v : 0.2f * v;
                    alpha[((size_t)(r0 + j) * 8 + b) * STR + t * 2 + h] = __expf(v - mx) / sm;
                }
            }
        }
    }
}

// ---------------- gather ----------------
template <int TIN>
__global__ void k_gather(const float* __restrict__ feat, const float* __restrict__ alpha,
                         const int* __restrict__ rowptr, const int* __restrict__ col,
                         const float* __restrict__ bias, float* __restrict__ y) {
    const int STR = 2 * TIN;
    int n = blockIdx.x, b = blockIdx.y;
    int c = threadIdx.x;  // 64
    int r0 = rowptr[n], deg = rowptr[n + 1] - r0;
    float acc[STR];
#pragma unroll
    for (int i = 0; i < STR; i++) acc[i] = 0.f;
    for (int j = 0; j < deg; j++) {
        int s = col[r0 + j];
        float av[STR];
        const float4* ap = (const float4*)&alpha[((size_t)(r0 + j) * 8 + b) * STR];
#pragma unroll
        for (int q = 0; q < STR / 4; q++) ((float4*)av)[q] = ap[q];
        const float* fp = feat + ((size_t)s * 8 + b) * (TIN * 128) + c;
#pragma unroll
        for (int t = 0; t < TIN; t++) {
#pragma unroll
            for (int h = 0; h < 2; h++)
                acc[t * 2 + h] += av[t * 2 + h] * fp[t * 128 + h * 64];
        }
    }
#pragma unroll
    for (int t = 0; t < TIN; t++) {
#pragma unroll
        for (int h = 0; h < 2; h++) {
            float v = acc[t * 2 + h] + bias[h * 64 + c];
            v = v > 0.f ? v : 0.f;
            y[((size_t)(b * 2 * TIN + t * 2 + h) * 2048 + n) * 64 + c] = v;
        }
    }
}

// ---------------- conv1: split-tf32 wmma, LN2 fused ----------------
__global__ __launch_bounds__(256) void k_conv1(
        const float* __restrict__ z, const float* __restrict__ wtm,
        const float* __restrict__ tb1, float* __restrict__ o1,
        const float* __restrict__ lnw, const float* __restrict__ lnb,
        const double* __restrict__ stat) {
    int b = blockIdx.x >> 8;
    int nt = blockIdx.x & 255;
    int n0 = nt * 8;
    __shared__ __align__(16) float abuf[96 * 72];
    __shared__ float muv[16], rsv[16];
    if (threadIdx.x < 16)
        ln_combine(stat, b * 16 + threadIdx.x, muv[threadIdx.x], rsv[threadIdx.x]);
    int w = threadIdx.x >> 5;
    int nw = w & 3;
    int mw0 = w >> 2;
    wmma::fragment<wmma::accumulator, 16, 16, 8, float> cfrag[3];
#pragma unroll
    for (int i = 0; i < 3; i++) wmma::fill_fragment(cfrag[i], 0.f);
    for (int k = 0; k < 5; k++) {
        __syncthreads();
        for (int i = threadIdx.x; i < 96 * 64; i += 256) {
            int r = i >> 6, ci = i & 63;
            int j = r >> 3, nn = r & 7;
            int t = j + k;
            float v = z[((size_t)((b * 16 + t) * 2048 + n0 + nn)) * 64 + ci];
            v = (v - muv[t]) * rsv[t] * lnw[(n0 + nn) * 64 + ci] + lnb[(n0 + nn) * 64 + ci];
            abuf[r * 72 + ci] = v;
        }
        __syncthreads();
#pragma unroll
        for (int kk = 0; kk < 8; kk++) {
            wmma::fragment<wmma::matrix_b, 16, 16, 8, wmma::precision::tf32, wmma::row_major> bf, bh, bl;
            wmma::load_matrix_sync(bf, wtm + (size_t)(k * 64 + kk * 8) * 64 + nw * 16, 64);
            split_frag(bf, bh, bl);
#pragma unroll
            for (int i = 0; i < 3; i++) {
                int mw = mw0 + 2 * i;
                wmma::fragment<wmma::matrix_a, 16, 16, 8, wmma::precision::tf32, wmma::row_major> af, ah, al_;
                wmma::load_matrix_sync(af, abuf + mw * 16 * 72 + kk * 8, 72);
                split_frag(af, ah, al_);
                wmma::mma_sync(cfrag[i], ah, bh, cfrag[i]);
                wmma::mma_sync(cfrag[i], ah, bl, cfrag[i]);
                wmma::mma_sync(cfrag[i], al_, bh, cfrag[i]);
            }
        }
    }
    __syncthreads();
#pragma unroll
    for (int i = 0; i < 3; i++) {
        int mw = mw0 + 2 * i;
        wmma::store_matrix_sync(abuf + mw * 16 * 72 + nw * 16, cfrag[i], 72, wmma::mem_row_major);
    }
    __syncthreads();
    for (int i = threadIdx.x; i < 96 * 64; i += 256) {
        int r = i >> 6, co = i & 63;
        int j = r >> 3, nn = r & 7;
        o1[((size_t)((b * 12 + j) * 2048 + n0 + nn)) * 64 + co] = abuf[r * 72 + co] + tb1[co];
    }
}

// ---------------- final FC (scrambled reshape + tc2 bias fused) ----------------
__global__ void k_fc(const float* __restrict__ o2, const float* __restrict__ tb2,
                     const float* __restrict__ fw, const float* __restrict__ fb,
                     float* __restrict__ out) {
    int b = blockIdx.x >> 5, q = blockIdx.x & 31;
    __shared__ float s[64 * 64];
    int c = threadIdx.x & 63;
    int rb = threadIdx.x >> 6;
    float acc[3] = {0.f, 0.f, 0.f};
    for (int j = 0; j < 12; j++) {
        __syncthreads();
        for (int i = threadIdx.x; i < 4096; i += 256)
            s[i] = o2[((size_t)((b * 12 + j) * 2048 + q * 64)) * 64 + i] + tb2[i & 63];
        __syncthreads();
        for (int rn = 0; rn < 64; rn++) {
            float v = s[rn * 64 + c];
#pragma unroll
            for (int rr = 0; rr < 3; rr++)
                acc[rr] += v * fw[(rb * 3 + rr) * 768 + rn * 12 + j];
        }
    }
    int np = 32 * c + q;
#pragma unroll
    for (int rr = 0; rr < 3; rr++) {
        int r = rb * 3 + rr;
        out[((size_t)b * 2048 + np) * 12 + r] = acc[rr] + fb[r];
    }
}

// ---------------- host ----------------
static void* sym(const void* s) {
    void* p = nullptr;
    cudaGetSymbolAddress(&p, s);
    return p;
}

extern "C" void kernel_launch(void* const* d_in, const int* in_sizes, int n_in,
                              void* d_out, int out_size) {
    const float* x = (const float*)d_in[0];
    const int* src = (const int*)d_in[1];
    const int* dst = (const int*)d_in[2];
    const float* W1 = (const float*)d_in[3];
    const float* al1 = (const float*)d_in[4];
    const float* ar1 = (const float*)d_in[5];
    const float* b1 = (const float*)d_in[6];
    const float* W2 = (const float*)d_in[7];
    const float* al2 = (const float*)d_in[8];
    const float* ar2 = (const float*)d_in[9];
    const float* b2 = (const float*)d_in[10];
    const float* ln1w = (const float*)d_in[11];
    const float* ln1b = (const float*)d_in[12];
    const float* ln2w = (const float*)d_in[13];
    const float* ln2b = (const float*)d_in[14];
    const float* tc1w = (const float*)d_in[15];
    const float* tc1b = (const float*)d_in[16];
    const float* ln3w = (const float*)d_in[17];
    const float* ln3b = (const float*)d_in[18];
    const float* tc2w = (const float*)d_in[19];
    const float* tc2b = (const float*)d_in[20];
    const float* fcw = (const float*)d_in[21];
    const float* fcb = (const float*)d_in[22];
    int E = in_sizes[1];

    float* xT = (float*)sym(g_xT);
    float* feat = (float*)sym(g_feat);
    float* el = (float*)sym(g_el);
    float* er = (float*)sym(g_er);
    float* alpha = (float*)sym(g_alpha);
    float* y = (float*)sym(g_y);
    float* z = (float*)sym(g_z);
    float* o1 = (float*)sym(g_o1);
    float* o2 = (float*)sym(g_o2);
    float* wtm = (float*)sym(g_wtm);
    float* wp1 = (float*)sym(g_wp1);
    float* wtm2 = (float*)sym(g_wtm2);
    double* stat = (double*)sym(g_stat);
    int* deg = (int*)sym(g_deg);
    int* cursor = (int*)sym(g_cursor);
    int* rowptr = (int*)sym(g_rowptr);
    int* col = (int*)sym(g_col);
    float* out = (float*)d_out;

    // slots 1-3 setup so capture slot #4 = gemm1
    k_transpose_x<<<16384, 256>>>(x, xT, deg);                         // 1
    k_count<<<(E + 255) / 256, 256>>>(dst, deg, E);                    // 2
    k_packw128<<<32, 256>>>(W1, wp1);                                  // 3
    k_gemm1<4><<<1024, 256>>>(xT, wp1, feat, al1, ar1, el, er);        // 4 <- ncu capture
    k_scan<<<1, 1024>>>(deg, rowptr, cursor);                          // 5
    k_fill_atomic<<<(E + 255) / 256, 256>>>(dst, src, cursor, col, E); // 6
    k_sortcol<<<8, 256>>>(rowptr, col);                                // 7

    // ---- GAT layer 1 ----
    k_alpha<4><<<2048, 256>>>(el, er, rowptr, col, alpha);
    {
        dim3 g(2048, 8);
        k_gather<4><<<g, 64>>>(feat, alpha, rowptr, col, b1, y);
    }
    k_lnpart<<<256, 1024>>>(y, stat);

    // ---- GAT layer 2 (LN1 fused into wmma GEMM input) ----
    k_wgemm2<<<1024, 256>>>(y, W2, feat, ln1w, ln1b, stat);
    k_elr2<<<16384, 256>>>(feat, al2, ar2, el, er);
    k_alpha<8><<<2048, 256>>>(el, er, rowptr, col, alpha);
    {
        dim3 g(2048, 8);
        k_gather<8><<<g, 64>>>(feat, alpha, rowptr, col, b2, z);
    }
    k_lnpart<<<512, 1024>>>(z, stat);

    // ---- output layer ----
    k_twm<<<80, 256>>>(tc1w, wtm);
    k_tw2<<<16, 256>>>(tc2w, wtm2);
    k_conv1<<<2048, 256>>>(z, wtm, tc1b, o1, ln2w, ln2b, stat);        // LN2 fused, split-tf32
    k_lnpart<<<384, 1024>>>(o1, stat);
    k_wgemm3<<<1536, 256>>>(o1, wtm2, o2, ln3w, ln3b, stat);           // LN3 fused, split-tf32
    k_fc<<<256, 256>>>(o2, tc2b, fcw, fcb, out);
}

// round 12
// speedup vs baseline: 1.0187x; 1.0187x over previous
#include <cuda_runtime.h>
#include <cuda_bf16.h>
#include <mma.h>
#include <math.h>

using namespace nvcuda;

#define NN_ 2048
#define BB_ 8

typedef unsigned long long ull;

__device__ __forceinline__ ull pk2(float x, float y) {
    ull r; asm("mov.b64 %0,{%1,%2};" : "=l"(r) : "f"(x), "f"(y)); return r;
}
__device__ __forceinline__ ull dup2(float x) { return pk2(x, x); }
__device__ __forceinline__ void fma2(ull& d, ull a, ull b) {
    asm("fma.rn.f32x2 %0,%1,%2,%0;" : "+l"(d) : "l"(a), "l"(b));
}
__device__ __forceinline__ float2 unpk2(ull v) {
    float2 f; asm("mov.b64 {%0,%1},%2;" : "=f"(f.x), "=f"(f.y) : "l"(v)); return f;
}
__device__ __forceinline__ void lds128(ull& a, ull& b, const float* p) {
    unsigned addr = (unsigned)__cvta_generic_to_shared((void*)p);
    asm("ld.shared.v2.b64 {%0,%1},[%2];" : "=l"(a), "=l"(b) : "r"(addr));
}
__device__ __forceinline__ float wred(float v) {
#pragma unroll
    for (int o = 16; o; o >>= 1) v += __shfl_xor_sync(0xFFFFFFFFu, v, o);
    return v;
}

// ---------------- scratch ----------------
__device__ float g_xT[4194304];      // [B,4,N,C]
__device__ float g_feat[16777216];   // node-major [n][b][t][128]
__device__ float g_el[262144];       // [b,t,n,2]
__device__ float g_er[262144];
__device__ float g_alpha[1310720];   // [e][b][2*TIN]
__device__ float g_y[16777216];      // [b,8,n,64]
__device__ float g_z[16777216];      // [b,16,n,64]
__device__ float g_o1[12582912];     // [b,12,n,64]
__device__ float g_o2[12582912];
__device__ float g_wtm[20480];       // conv1 weights [k*64+ci][co]
__device__ float g_wp1[8192];        // W1 packed [k][lane32][4]
__device__ float g_wp2[8192];        // W2 packed [k][lane32][4]
__device__ float g_wpt2[4096];       // tc2 packed [k=ci][lane32][2]
__device__ double g_stat[1024];
__device__ int   g_deg[2048];
__device__ int   g_cursor[2048];
__device__ int   g_rowptr[2049];
__device__ int   g_col[16384];

// ---------------- transpose x (+ zero deg) ----------------
__global__ void k_transpose_x(const float* __restrict__ x, float* __restrict__ xT,
                              int* __restrict__ deg) {
    int i = blockIdx.x * 256 + threadIdx.x;
    if (i < 2048) deg[i] = 0;
    if (i >= BB_ * NN_ * 4 * 64) return;
    int c = i & 63;
    int t = (i >> 6) & 3;
    int n = (i >> 8) & 2047;
    int b = i >> 19;
    xT[((size_t)(b * 4 + t) * 2048 + n) * 64 + c] = x[i];
}

// ---------------- CSR build ----------------
__global__ void k_count(const int* __restrict__ dst, int* __restrict__ deg, int E) {
    int e = blockIdx.x * 256 + threadIdx.x;
    if (e < E) atomicAdd(&deg[dst[e]], 1);
}

__global__ void k_scan(const int* __restrict__ deg, int* __restrict__ rowptr,
                       int* __restrict__ cursor) {
    __shared__ int s[2048];
    int tid = threadIdx.x;
    s[tid] = deg[tid];
    s[tid + 1024] = deg[tid + 1024];
    __syncthreads();
    for (int off = 1; off < 2048; off <<= 1) {
        int i0 = tid, i1 = tid + 1024;
        int a0 = (i0 >= off) ? s[i0 - off] : 0;
        int a1 = (i1 >= off) ? s[i1 - off] : 0;
        __syncthreads();
        s[i0] += a0; s[i1] += a1;
        __syncthreads();
    }
    rowptr[tid + 1] = s[tid];
    rowptr[tid + 1025] = s[tid + 1024];
    if (tid == 0) { rowptr[0] = 0; cursor[0] = 0; }
    if (tid < 1023) cursor[tid + 1] = s[tid];
    cursor[tid + 1024] = s[tid + 1023];
}

__global__ void k_fill_atomic(const int* __restrict__ dst, const int* __restrict__ src,
                              int* __restrict__ cursor, int* __restrict__ col, int E) {
    int e = blockIdx.x * 256 + threadIdx.x;
    if (e >= E) return;
    int pos = atomicAdd(&cursor[dst[e]], 1);
    col[pos] = src[e];
}

__global__ void k_sortcol(const int* __restrict__ rowptr, int* __restrict__ col) {
    int n = blockIdx.x * 256 + threadIdx.x;
    if (n >= NN_) return;
    int r0 = rowptr[n], r1 = rowptr[n + 1];
    for (int i = r0 + 1; i < r1; i++) {
        int v = col[i];
        int j = i - 1;
        while (j >= r0 && col[j] > v) { col[j + 1] = col[j]; j--; }
        col[j + 1] = v;
    }
}

// ---------------- weight prep ----------------
// tc1w [co][ci][5] -> wtm [k*64+ci][co]  (conv1 wmma B matrix)
__global__ void k_twm(const float* __restrict__ w, float* __restrict__ wtm) {
    int i = blockIdx.x * 256 + threadIdx.x;
    if (i >= 20480) return;
    int co = i & 63;
    int ci = (i >> 6) & 63;
    int k = i >> 12;
    wtm[(k * 64 + ci) * 64 + co] = w[(co * 64 + ci) * 5 + k];
}

__global__ void k_packw128(const float* __restrict__ w, float* __restrict__ wp) {
    int i = blockIdx.x * 256 + threadIdx.x;
    if (i >= 8192) return;
    int k = i >> 7, rem = i & 127, j = rem >> 5, lane = rem & 31;
    wp[(k * 32 + lane) * 4 + j] = w[i];
}

__global__ void k_packw64(const float* __restrict__ w, float* __restrict__ wp) {
    int i = blockIdx.x * 256 + threadIdx.x;
    if (i >= 4096) return;
    int ci = i >> 6, rem = i & 63, j = rem >> 5, lane = rem & 31;
    wp[(ci * 32 + lane) * 2 + j] = w[(lane + 32 * j) * 64 + ci];
}

// ---------------- LN partial stats ----------------
__global__ void k_lnpart(const float* __restrict__ x, double* __restrict__ stat) {
    int slice = blockIdx.x >> 2, q = blockIdx.x & 3;
    const float* xs = x + (size_t)slice * 131072 + q * 32768;
    double s1 = 0.0, s2 = 0.0;
    for (int i = threadIdx.x; i < 32768; i += 1024) {
        float v = xs[i];
        s1 += v;
        s2 += (double)v * (double)v;
    }
    for (int o = 16; o; o >>= 1) {
        s1 += __shfl_xor_sync(0xFFFFFFFFu, s1, o);
        s2 += __shfl_xor_sync(0xFFFFFFFFu, s2, o);
    }
    __shared__ double sh1[32], sh2[32];
    int wid = threadIdx.x >> 5, lane = threadIdx.x & 31;
    if (!lane) { sh1[wid] = s1; sh2[wid] = s2; }
    __syncthreads();
    if (threadIdx.x == 0) {
        double t1 = 0, t2 = 0;
        for (int k = 0; k < 32; k++) { t1 += sh1[k]; t2 += sh2[k]; }
        stat[slice * 8 + q * 2] = t1;
        stat[slice * 8 + q * 2 + 1] = t2;
    }
}

__device__ __forceinline__ void ln_combine(const double* __restrict__ stat, int slice,
                                           float& mu, float& rs) {
    double t1 = 0, t2 = 0;
#pragma unroll
    for (int q = 0; q < 4; q++) {
        t1 += stat[slice * 8 + q * 2];
        t2 += stat[slice * 8 + q * 2 + 1];
    }
    double m = t1 / 131072.0;
    double var = t2 / 131072.0 - m * m;
    mu = (float)m;
    rs = (float)rsqrt(var + 1e-5);
}

// split-tf32 helper
template <typename Frag>
__device__ __forceinline__ void split_frag(const Frag& f, Frag& hi, Frag& lo) {
#pragma unroll
    for (int t = 0; t < f.num_elements; t++) {
        float v = f.x[t];
        float h = wmma::__float_to_tf32(v);
        hi.x[t] = h;
        lo.x[t] = wmma::__float_to_tf32(v - h);
    }
}

// ---------------- warp-tiled GEMM (R8 config): 16 rows x CO per warp, 128 rows/block ----------------
template <int CO, bool ELR, bool LNIN, int TIN>
__global__ __launch_bounds__(256) void k_gemm(
        const float* __restrict__ in, const float* __restrict__ wp,
        const float* __restrict__ bias, float* __restrict__ out,
        const float* __restrict__ al, const float* __restrict__ ar,
        float* __restrict__ el, float* __restrict__ er,
        const float* __restrict__ lnw, const float* __restrict__ lnb,
        const double* __restrict__ stat) {
    const int CPT = CO / 32;           // 4 or 2
    size_t m0 = (size_t)blockIdx.x * 128;
    int tid = threadIdx.x;
    int warp = tid >> 5, lane = tid & 31;
    __shared__ __align__(16) float xs[64 * 128];   // [k][row]
    __shared__ float mu_s, rs_s;
    if (LNIN) {
        if (tid == 0) ln_combine(stat, (int)(m0 >> 11), mu_s, rs_s);
        __syncthreads();
    }
    float mu = LNIN ? mu_s : 0.f, rs = LNIN ? rs_s : 1.f;
    for (int i = tid; i < 128 * 64; i += 256) {
        int r = i >> 6, k = i & 63;
        float v = in[m0 * 64 + i];
        if (LNIN) {
            int n = (int)((m0 + r) & 2047);
            v = (v - mu) * rs * lnw[n * 64 + k] + lnb[n * 64 + k];
        }
        xs[k * 128 + r] = v;
    }
    __syncthreads();
    int rbase = warp * 16;
    ull acc[8][CPT];
#pragma unroll
    for (int p = 0; p < 8; p++)
#pragma unroll
        for (int j = 0; j < CPT; j++) acc[p][j] = 0ull;
#pragma unroll 4
    for (int k = 0; k < 64; k++) {
        ull xv[8];
        const float* xp = &xs[k * 128 + rbase];
        lds128(xv[0], xv[1], xp);
        lds128(xv[2], xv[3], xp + 4);
        lds128(xv[4], xv[5], xp + 8);
        lds128(xv[6], xv[7], xp + 12);
        ull wd[CPT];
        if (CPT == 4) {
            float4 w4 = *(const float4*)&wp[(k * 32 + lane) * 4];
            wd[0] = dup2(w4.x); wd[1] = dup2(w4.y); wd[2] = dup2(w4.z); wd[3] = dup2(w4.w);
        } else {
            float2 w2 = *(const float2*)&wp[(k * 32 + lane) * 2];
            wd[0] = dup2(w2.x); wd[1] = dup2(w2.y);
        }
#pragma unroll
        for (int p = 0; p < 8; p++)
#pragma unroll
            for (int j = 0; j < CPT; j++) fma2(acc[p][j], xv[p], wd[j]);
    }
    if (ELR) {
        const size_t rowstride = (size_t)8 * TIN * 128;
        size_t base = (size_t)(m0 & 2047) * rowstride + (size_t)(m0 >> 11) * 128;
        float al0 = al[lane], al1 = al[lane + 32], al2v = al[lane + 64], al3 = al[lane + 96];
        float ar0 = ar[lane], ar1 = ar[lane + 32], ar2v = ar[lane + 64], ar3 = ar[lane + 96];
#pragma unroll
        for (int p = 0; p < 8; p++) {
            float2 v0 = unpk2(acc[p][0]);
            float2 v1 = unpk2(acc[p][1]);
            float2 v2 = unpk2(acc[p][2]);
            float2 v3 = unpk2(acc[p][3]);
            size_t a0 = base + (size_t)(rbase + 2 * p) * rowstride;
            size_t a1 = a0 + rowstride;
            out[a0 + lane] = v0.x; out[a0 + lane + 32] = v1.x;
            out[a0 + lane + 64] = v2.x; out[a0 + lane + 96] = v3.x;
            out[a1 + lane] = v0.y; out[a1 + lane + 32] = v1.y;
            out[a1 + lane + 64] = v2.y; out[a1 + lane + 96] = v3.y;
            float sl0x = wred(v0.x * al0 + v1.x * al1);
            float sl1x = wred(v2.x * al2v + v3.x * al3);
            float sr0x = wred(v0.x * ar0 + v1.x * ar1);
            float sr1x = wred(v2.x * ar2v + v3.x * ar3);
            float sl0y = wred(v0.y * al0 + v1.y * al1);
            float sl1y = wred(v2.y * al2v + v3.y * al3);
            float sr0y = wred(v0.y * ar0 + v1.y * ar1);
            float sr1y = wred(v2.y * ar2v + v3.y * ar3);
            if (lane == 0) {
                size_t rA = m0 + rbase + 2 * p;
                el[rA * 2 + 0] = sl0x; el[rA * 2 + 1] = sl1x;
                er[rA * 2 + 0] = sr0x; er[rA * 2 + 1] = sr1x;
                el[(rA + 1) * 2 + 0] = sl0y; el[(rA + 1) * 2 + 1] = sl1y;
                er[(rA + 1) * 2 + 0] = sr0y; er[(rA + 1) * 2 + 1] = sr1y;
            }
        }
    } else {
        float bv0 = bias[lane], bv1 = bias[lane + 32];
#pragma unroll
        for (int p = 0; p < 8; p++) {
            float2 v0 = unpk2(acc[p][0]);
            float2 v1 = unpk2(acc[p][1]);
            size_t r0 = m0 + rbase + 2 * p;
            out[r0 * 64 + lane] = v0.x + bv0;
            out[r0 * 64 + lane + 32] = v1.x + bv1;
            out[(r0 + 1) * 64 + lane] = v0.y + bv0;
            out[(r0 + 1) * 64 + lane + 32] = v1.y + bv1;
        }
    }
}

// ---------------- edge softmax alpha: [e][b][2*TIN] ----------------
template <int TIN>
__global__ void k_alpha(const float* __restrict__ el, const float* __restrict__ er,
                        const int* __restrict__ rowptr, const int* __restrict__ col,
                        float* __restrict__ alpha) {
    const int STR = 2 * TIN;
    int gw = blockIdx.x * 8 + (threadIdx.x >> 5);
    int n = gw >> 3, b = gw & 7;
    int lane = threadIdx.x & 31;
    int r0 = rowptr[n], deg = rowptr[n + 1] - r0;
    const float2* el2 = (const float2*)el;
    const float2* er2 = (const float2*)er;
    if (deg <= 32) {
        int s = (lane < deg) ? col[r0 + lane] : 0;
        float av[STR];
        for (int t = 0; t < TIN; t++) {
            int base = (b * TIN + t) * 2048;
            float2 erd = er2[base + n];
            float2 ela = (lane < deg) ? el2[base + s] : make_float2(-3.0e38f, -3.0e38f);
#pragma unroll
            for (int h = 0; h < 2; h++) {
                float v = (h ? ela.y + erd.y : ela.x + erd.x);
                float e = (lane < deg) ? (v > 0.f ? v : 0.2f * v) : -3.0e38f;
                float mx = e;
                for (int o = 16; o; o >>= 1) mx = fmaxf(mx, __shfl_xor_sync(0xFFFFFFFFu, mx, o));
                float a = (lane < deg) ? __expf(e - mx) : 0.f;
                float sm = a;
                for (int o = 16; o; o >>= 1) sm += __shfl_xor_sync(0xFFFFFFFFu, sm, o);
                av[t * 2 + h] = a / sm;
            }
        }
        if (lane < deg) {
            float4* ap = (float4*)&alpha[((size_t)(r0 + lane) * 8 + b) * STR];
#pragma unroll
            for (int q = 0; q < STR / 4; q++) ap[q] = ((float4*)av)[q];
        }
    } else {
        for (int t = 0; t < TIN; t++) {
            int base = (b * TIN + t) * 2048;
            for (int h = 0; h < 2; h++) {
                float erd = er[(size_t)(base + n) * 2 + h];
                float mx = -3.0e38f;
                for (int j = lane; j < deg; j += 32) {
                    float v = el[(size_t)(base + col[r0 + j]) * 2 + h] + erd;
                    v = v > 0.f ? v : 0.2f * v;
                    mx = fmaxf(mx, v);
                }
                for (int o = 16; o; o >>= 1) mx = fmaxf(mx, __shfl_xor_sync(0xFFFFFFFFu, mx, o));
                float sm = 0.f;
                for (int j = lane; j < deg; j += 32) {
                    float v = el[(size_t)(base + col[r0 + j]) * 2 + h] + erd;
                    v = v > 0.f ? v : 0.2f * v;
                    sm += __expf(v - mx);
                }
                for (int o = 16; o; o >>= 1) sm += __shfl_xor_sync(0xFFFFFFFFu, sm, o);
                for (int j = lane; j < deg; j += 32) {
                    float v = el[(size_t)(base + col[r0 + j]) * 2 + h] + erd;
                    v = v > 0.f ? v : 0.2f * v;
                    alpha[((size_t)(r0 + j) * 8 + b) * STR + t * 2 + h] = __expf(v - mx) / sm;
                }
            }
        }
    }
}

// ---------------- gather ----------------
template <int TIN>
__global__ void k_gather(const float* __restrict__ feat, const float* __restrict__ alpha,
                         const int* __restrict__ rowptr, const int* __restrict__ col,
                         const float* __restrict__ bias, float* __restrict__ y) {
    const int STR = 2 * TIN;
    int n = blockIdx.x, b = blockIdx.y;
    int c = threadIdx.x;  // 64
    int r0 = rowptr[n], deg = rowptr[n + 1] - r0;
    float acc[STR];
#pragma unroll
    for (int i = 0; i < STR; i++) acc[i] = 0.f;
    for (int j = 0; j < deg; j++) {
        int s = col[r0 + j];
        float av[STR];
        const float4* ap = (const float4*)&alpha[((size_t)(r0 + j) * 8 + b) * STR];
#pragma unroll
        for (int q = 0; q < STR / 4; q++) ((float4*)av)[q] = ap[q];
        const float* fp = feat + ((size_t)s * 8 + b) * (TIN * 128) + c;
#pragma unroll
        for (int t = 0; t < TIN; t++) {
#pragma unroll
            for (int h = 0; h < 2; h++)
                acc[t * 2 + h] += av[t * 2 + h] * fp[t * 128 + h * 64];
        }
    }
#pragma unroll
    for (int t = 0; t < TIN; t++) {
#pragma unroll
        for (int h = 0; h < 2; h++) {
            float v = acc[t * 2 + h] + bias[h * 64 + c];
            v = v > 0.f ? v : 0.f;
            y[((size_t)(b * 2 * TIN + t * 2 + h) * 2048 + n) * 64 + c] = v;
        }
    }
}

// ---------------- conv1: split-tf32 wmma, LN2 fused (R11 version, measured good) ----------------
__global__ __launch_bounds__(256) void k_conv1(
        const float* __restrict__ z, const float* __restrict__ wtm,
        const float* __restrict__ tb1, float* __restrict__ o1,
        const float* __restrict__ lnw, const float* __restrict__ lnb,
        const double* __restrict__ stat) {
    int b = blockIdx.x >> 8;
    int nt = blockIdx.x & 255;
    int n0 = nt * 8;
    __shared__ __align__(16) float abuf[96 * 72];
    __shared__ float muv[16], rsv[16];
    if (threadIdx.x < 16)
        ln_combine(stat, b * 16 + threadIdx.x, muv[threadIdx.x], rsv[threadIdx.x]);
    int w = threadIdx.x >> 5;
    int nw = w & 3;
    int mw0 = w >> 2;
    wmma::fragment<wmma::accumulator, 16, 16, 8, float> cfrag[3];
#pragma unroll
    for (int i = 0; i < 3; i++) wmma::fill_fragment(cfrag[i], 0.f);
    for (int k = 0; k < 5; k++) {
        __syncthreads();
        for (int i = threadIdx.x; i < 96 * 64; i += 256) {
            int r = i >> 6, ci = i & 63;
            int j = r >> 3, nn = r & 7;
            int t = j + k;
            float v = z[((size_t)((b * 16 + t) * 2048 + n0 + nn)) * 64 + ci];
            v = (v - muv[t]) * rsv[t] * lnw[(n0 + nn) * 64 + ci] + lnb[(n0 + nn) * 64 + ci];
            abuf[r * 72 + ci] = v;
        }
        __syncthreads();
#pragma unroll
        for (int kk = 0; kk < 8; kk++) {
            wmma::fragment<wmma::matrix_b, 16, 16, 8, wmma::precision::tf32, wmma::row_major> bf, bh, bl;
            wmma::load_matrix_sync(bf, wtm + (size_t)(k * 64 + kk * 8) * 64 + nw * 16, 64);
            split_frag(bf, bh, bl);
#pragma unroll
            for (int i = 0; i < 3; i++) {
                int mw = mw0 + 2 * i;
                wmma::fragment<wmma::matrix_a, 16, 16, 8, wmma::precision::tf32, wmma::row_major> af, ah, al_;
                wmma::load_matrix_sync(af, abuf + mw * 16 * 72 + kk * 8, 72);
                split_frag(af, ah, al_);
                wmma::mma_sync(cfrag[i], ah, bh, cfrag[i]);
                wmma::mma_sync(cfrag[i], ah, bl, cfrag[i]);
                wmma::mma_sync(cfrag[i], al_, bh, cfrag[i]);
            }
        }
    }
    __syncthreads();
#pragma unroll
    for (int i = 0; i < 3; i++) {
        int mw = mw0 + 2 * i;
        wmma::store_matrix_sync(abuf + mw * 16 * 72 + nw * 16, cfrag[i], 72, wmma::mem_row_major);
    }
    __syncthreads();
    for (int i = threadIdx.x; i < 96 * 64; i += 256) {
        int r = i >> 6, co = i & 63;
        int j = r >> 3, nn = r & 7;
        o1[((size_t)((b * 12 + j) * 2048 + n0 + nn)) * 64 + co] = abuf[r * 72 + co] + tb1[co];
    }
}

// ---------------- final FC (scrambled reshape fused) ----------------
__global__ void k_fc(const float* __restrict__ o2, const float* __restrict__ fw,
                     const float* __restrict__ fb, float* __restrict__ out) {
    int b = blockIdx.x >> 5, q = blockIdx.x & 31;
    __shared__ float s[64 * 64];
    int c = threadIdx.x & 63;
    int rb = threadIdx.x >> 6;
    float acc[3] = {0.f, 0.f, 0.f};
    for (int j = 0; j < 12; j++) {
        __syncthreads();
        for (int i = threadIdx.x; i < 4096; i += 256)
            s[i] = o2[((size_t)((b * 12 + j) * 2048 + q * 64)) * 64 + i];
        __syncthreads();
        for (int rn = 0; rn < 64; rn++) {
            float v = s[rn * 64 + c];
#pragma unroll
            for (int rr = 0; rr < 3; rr++)
                acc[rr] += v * fw[(rb * 3 + rr) * 768 + rn * 12 + j];
        }
    }
    int np = 32 * c + q;
#pragma unroll
    for (int rr = 0; rr < 3; rr++) {
        int r = rb * 3 + rr;
        out[((size_t)b * 2048 + np) * 12 + r] = acc[rr] + fb[r];
    }
}

// ---------------- host ----------------
static void* sym(const void* s) {
    void* p = nullptr;
    cudaGetSymbolAddress(&p, s);
    return p;
}

extern "C" void kernel_launch(void* const* d_in, const int* in_sizes, int n_in,
                              void* d_out, int out_size) {
    const float* x = (const float*)d_in[0];
    const int* src = (const int*)d_in[1];
    const int* dst = (const int*)d_in[2];
    const float* W1 = (const float*)d_in[3];
    const float* al1 = (const float*)d_in[4];
    const float* ar1 = (const float*)d_in[5];
    const float* b1 = (const float*)d_in[6];
    const float* W2 = (const float*)d_in[7];
    const float* al2 = (const float*)d_in[8];
    const float* ar2 = (const float*)d_in[9];
    const float* b2 = (const float*)d_in[10];
    const float* ln1w = (const float*)d_in[11];
    const float* ln1b = (const float*)d_in[12];
    const float* ln2w = (const float*)d_in[13];
    const float* ln2b = (const float*)d_in[14];
    const float* tc1w = (const float*)d_in[15];
    const float* tc1b = (const float*)d_in[16];
    const float* ln3w = (const float*)d_in[17];
    const float* ln3b = (const float*)d_in[18];
    const float* tc2w = (const float*)d_in[19];
    const float* tc2b = (const float*)d_in[20];
    const float* fcw = (const float*)d_in[21];
    const float* fcb = (const float*)d_in[22];
    int E = in_sizes[1];

    float* xT = (float*)sym(g_xT);
    float* feat = (float*)sym(g_feat);
    float* el = (float*)sym(g_el);
    float* er = (float*)sym(g_er);
    float* alpha = (float*)sym(g_alpha);
    float* y = (float*)sym(g_y);
    float* z = (float*)sym(g_z);
    float* o1 = (float*)sym(g_o1);
    float* o2 = (float*)sym(g_o2);
    float* wtm = (float*)sym(g_wtm);
    float* wp1 = (float*)sym(g_wp1);
    float* wp2 = (float*)sym(g_wp2);
    float* wpt2 = (float*)sym(g_wpt2);
    double* stat = (double*)sym(g_stat);
    int* deg = (int*)sym(g_deg);
    int* cursor = (int*)sym(g_cursor);
    int* rowptr = (int*)sym(g_rowptr);
    int* col = (int*)sym(g_col);
    float* out = (float*)d_out;

    // slots 1-3 setup so capture slot #4 = gemm1
    k_transpose_x<<<16384, 256>>>(x, xT, deg);                         // 1
    k_count<<<(E + 255) / 256, 256>>>(dst, deg, E);                    // 2
    k_packw128<<<32, 256>>>(W1, wp1);                                  // 3
    k_gemm<128, true, false, 4><<<512, 256>>>(xT, wp1, nullptr, feat,  // 4 <- ncu capture
                                              al1, ar1, el, er, nullptr, nullptr, nullptr);
    k_scan<<<1, 1024>>>(deg, rowptr, cursor);                          // 5
    k_fill_atomic<<<(E + 255) / 256, 256>>>(dst, src, cursor, col, E); // 6
    k_sortcol<<<8, 256>>>(rowptr, col);                                // 7
    k_packw128<<<32, 256>>>(W2, wp2);                                  // 8

    // ---- GAT layer 1 ----
    k_alpha<4><<<2048, 256>>>(el, er, rowptr, col, alpha);
    {
        dim3 g(2048, 8);
        k_gather<4><<<g, 64>>>(feat, alpha, rowptr, col, b1, y);
    }
    k_lnpart<<<256, 1024>>>(y, stat);

    // ---- GAT layer 2 (LN1 fused into GEMM input) ----
    k_gemm<128, true, true, 8><<<1024, 256>>>(y, wp2, nullptr, feat, al2, ar2, el, er,
                                              ln1w, ln1b, stat);
    k_alpha<8><<<2048, 256>>>(el, er, rowptr, col, alpha);
    {
        dim3 g(2048, 8);
        k_gather<8><<<g, 64>>>(feat, alpha, rowptr, col, b2, z);
    }
    k_lnpart<<<512, 1024>>>(z, stat);

    // ---- output layer ----
    k_twm<<<80, 256>>>(tc1w, wtm);
    k_packw64<<<16, 256>>>(tc2w, wpt2);
    k_conv1<<<2048, 256>>>(z, wtm, tc1b, o1, ln2w, ln2b, stat);  // LN2 fused, split-tf32 wmma
    k_lnpart<<<384, 1024>>>(o1, stat);
    k_gemm<64, false, true, 0><<<1536, 256>>>(o1, wpt2, tc2b, o2, nullptr, nullptr, nullptr,
                                              nullptr, ln3w, ln3b, stat);  // LN3 fused
    k_fc<<<256, 256>>>(o2, fcw, fcb, out);
}

// round 13
// speedup vs baseline: 1.2586x; 1.2355x over previous
#include <cuda_runtime.h>
#include <cuda_bf16.h>
#include <mma.h>
#include <math.h>

using namespace nvcuda;

#define NN_ 2048
#define BB_ 8

typedef unsigned long long ull;

__device__ __forceinline__ ull pk2(float x, float y) {
    ull r; asm("mov.b64 %0,{%1,%2};" : "=l"(r) : "f"(x), "f"(y)); return r;
}
__device__ __forceinline__ ull dup2(float x) { return pk2(x, x); }
__device__ __forceinline__ void fma2(ull& d, ull a, ull b) {
    asm("fma.rn.f32x2 %0,%1,%2,%0;" : "+l"(d) : "l"(a), "l"(b));
}
__device__ __forceinline__ float2 unpk2(ull v) {
    float2 f; asm("mov.b64 {%0,%1},%2;" : "=f"(f.x), "=f"(f.y) : "l"(v)); return f;
}
__device__ __forceinline__ void lds128(ull& a, ull& b, const float* p) {
    unsigned addr = (unsigned)__cvta_generic_to_shared((void*)p);
    asm("ld.shared.v2.b64 {%0,%1},[%2];" : "=l"(a), "=l"(b) : "r"(addr));
}
__device__ __forceinline__ float wred(float v) {
#pragma unroll
    for (int o = 16; o; o >>= 1) v += __shfl_xor_sync(0xFFFFFFFFu, v, o);
    return v;
}

// ---------------- scratch ----------------
__device__ float g_xT[4194304];      // [B,4,N,C]
__device__ float g_feat[16777216];   // node-major [n][b][t][128]
__device__ float g_el[262144];       // [b,t,n,2]
__device__ float g_er[262144];
__device__ float g_alpha[1310720];   // [e][b][2*TIN]
__device__ float g_y[16777216];      // [b,8,n,64]
__device__ float g_z[16777216];      // [b,16,n,64]
__device__ float g_o1[12582912];     // [b,12,n,64]
__device__ float g_o2[12582912];
__device__ float g_wtm[20480];       // conv1 weights [k*64+ci][co]
__device__ float g_wp1[8192];        // W1 packed [k][lane32][4]
__device__ float g_wp2[8192];        // W2 packed [k][lane32][4]
__device__ float g_wpt2[4096];       // tc2 packed [k=ci][lane32][2]
__device__ double g_stat[1024];
__device__ int   g_deg[2048];
__device__ int   g_cursor[2048];
__device__ int   g_rowptr[2049];
__device__ int   g_col[16384];

// ---------------- transpose x (+ zero deg) ----------------
__global__ void k_transpose_x(const float* __restrict__ x, float* __restrict__ xT,
                              int* __restrict__ deg) {
    int i = blockIdx.x * 256 + threadIdx.x;
    if (i < 2048) deg[i] = 0;
    if (i >= BB_ * NN_ * 4 * 64) return;
    int c = i & 63;
    int t = (i >> 6) & 3;
    int n = (i >> 8) & 2047;
    int b = i >> 19;
    xT[((size_t)(b * 4 + t) * 2048 + n) * 64 + c] = x[i];
}

// ---------------- CSR build ----------------
__global__ void k_count(const int* __restrict__ dst, int* __restrict__ deg, int E) {
    int e = blockIdx.x * 256 + threadIdx.x;
    if (e < E) atomicAdd(&deg[dst[e]], 1);
}

__global__ void k_scan(const int* __restrict__ deg, int* __restrict__ rowptr,
                       int* __restrict__ cursor) {
    __shared__ int s[2048];
    int tid = threadIdx.x;
    s[tid] = deg[tid];
    s[tid + 1024] = deg[tid + 1024];
    __syncthreads();
    for (int off = 1; off < 2048; off <<= 1) {
        int i0 = tid, i1 = tid + 1024;
        int a0 = (i0 >= off) ? s[i0 - off] : 0;
        int a1 = (i1 >= off) ? s[i1 - off] : 0;
        __syncthreads();
        s[i0] += a0; s[i1] += a1;
        __syncthreads();
    }
    rowptr[tid + 1] = s[tid];
    rowptr[tid + 1025] = s[tid + 1024];
    if (tid == 0) { rowptr[0] = 0; cursor[0] = 0; }
    if (tid < 1023) cursor[tid + 1] = s[tid];
    cursor[tid + 1024] = s[tid + 1023];
}

__global__ void k_fill_atomic(const int* __restrict__ dst, const int* __restrict__ src,
                              int* __restrict__ cursor, int* __restrict__ col, int E) {
    int e = blockIdx.x * 256 + threadIdx.x;
    if (e >= E) return;
    int pos = atomicAdd(&cursor[dst[e]], 1);
    col[pos] = src[e];
}

__global__ void k_sortcol(const int* __restrict__ rowptr, int* __restrict__ col) {
    int n = blockIdx.x * 256 + threadIdx.x;
    if (n >= NN_) return;
    int r0 = rowptr[n], r1 = rowptr[n + 1];
    for (int i = r0 + 1; i < r1; i++) {
        int v = col[i];
        int j = i - 1;
        while (j >= r0 && col[j] > v) { col[j + 1] = col[j]; j--; }
        col[j + 1] = v;
    }
}

// ---------------- weight prep ----------------
// tc1w [co][ci][5] -> wtm [k*64+ci][co]
__global__ void k_twm(const float* __restrict__ w, float* __restrict__ wtm) {
    int i = blockIdx.x * 256 + threadIdx.x;
    if (i >= 20480) return;
    int co = i & 63;
    int ci = (i >> 6) & 63;
    int k = i >> 12;
    wtm[(k * 64 + ci) * 64 + co] = w[(co * 64 + ci) * 5 + k];
}

__global__ void k_packw128(const float* __restrict__ w, float* __restrict__ wp) {
    int i = blockIdx.x * 256 + threadIdx.x;
    if (i >= 8192) return;
    int k = i >> 7, rem = i & 127, j = rem >> 5, lane = rem & 31;
    wp[(k * 32 + lane) * 4 + j] = w[i];
}

__global__ void k_packw64(const float* __restrict__ w, float* __restrict__ wp) {
    int i = blockIdx.x * 256 + threadIdx.x;
    if (i >= 4096) return;
    int ci = i >> 6, rem = i & 63, j = rem >> 5, lane = rem & 31;
    wp[(ci * 32 + lane) * 2 + j] = w[(lane + 32 * j) * 64 + ci];
}

// ---------------- LN partial stats ----------------
__global__ void k_lnpart(const float* __restrict__ x, double* __restrict__ stat) {
    int slice = blockIdx.x >> 2, q = blockIdx.x & 3;
    const float* xs = x + (size_t)slice * 131072 + q * 32768;
    double s1 = 0.0, s2 = 0.0;
    for (int i = threadIdx.x; i < 32768; i += 1024) {
        float v = xs[i];
        s1 += v;
        s2 += (double)v * (double)v;
    }
    for (int o = 16; o; o >>= 1) {
        s1 += __shfl_xor_sync(0xFFFFFFFFu, s1, o);
        s2 += __shfl_xor_sync(0xFFFFFFFFu, s2, o);
    }
    __shared__ double sh1[32], sh2[32];
    int wid = threadIdx.x >> 5, lane = threadIdx.x & 31;
    if (!lane) { sh1[wid] = s1; sh2[wid] = s2; }
    __syncthreads();
    if (threadIdx.x == 0) {
        double t1 = 0, t2 = 0;
        for (int k = 0; k < 32; k++) { t1 += sh1[k]; t2 += sh2[k]; }
        stat[slice * 8 + q * 2] = t1;
        stat[slice * 8 + q * 2 + 1] = t2;
    }
}

__device__ __forceinline__ void ln_combine(const double* __restrict__ stat, int slice,
                                           float& mu, float& rs) {
    double t1 = 0, t2 = 0;
#pragma unroll
    for (int q = 0; q < 4; q++) {
        t1 += stat[slice * 8 + q * 2];
        t2 += stat[slice * 8 + q * 2 + 1];
    }
    double m = t1 / 131072.0;
    double var = t2 / 131072.0 - m * m;
    mu = (float)m;
    rs = (float)rsqrt(var + 1e-5);
}

// ---------------- gemm1: 8 rows/warp, 64 rows/block (R9 variant, measured 52.7us) ----------------
template <int TIN>
__global__ __launch_bounds__(256, 3) void k_gemm8(
        const float* __restrict__ in, const float* __restrict__ wp,
        float* __restrict__ out, const float* __restrict__ al, const float* __restrict__ ar,
        float* __restrict__ el, float* __restrict__ er) {
    size_t m0 = (size_t)blockIdx.x * 64;
    int tid = threadIdx.x;
    int warp = tid >> 5, lane = tid & 31;
    __shared__ __align__(16) float xs[64 * 64];
    for (int i = tid; i < 64 * 64; i += 256) {
        int r = i >> 6, k = i & 63;
        xs[k * 64 + r] = in[m0 * 64 + i];
    }
    __syncthreads();
    int rbase = warp * 8;
    ull acc[4][4];
#pragma unroll
    for (int p = 0; p < 4; p++)
#pragma unroll
        for (int j = 0; j < 4; j++) acc[p][j] = 0ull;
#pragma unroll 8
    for (int k = 0; k < 64; k++) {
        ull xv[4];
        const float* xp = &xs[k * 64 + rbase];
        lds128(xv[0], xv[1], xp);
        lds128(xv[2], xv[3], xp + 4);
        float4 w4 = *(const float4*)&wp[(k * 32 + lane) * 4];
        ull wd[4] = {dup2(w4.x), dup2(w4.y), dup2(w4.z), dup2(w4.w)};
#pragma unroll
        for (int p = 0; p < 4; p++)
#pragma unroll
            for (int j = 0; j < 4; j++) fma2(acc[p][j], xv[p], wd[j]);
    }
    const size_t rowstride = (size_t)8 * TIN * 128;
    size_t base = (size_t)(m0 & 2047) * rowstride + (size_t)(m0 >> 11) * 128;
    float al0 = al[lane], al1 = al[lane + 32], al2v = al[lane + 64], al3 = al[lane + 96];
    float ar0 = ar[lane], ar1 = ar[lane + 32], ar2v = ar[lane + 64], ar3 = ar[lane + 96];
#pragma unroll
    for (int p = 0; p < 4; p++) {
        float2 v0 = unpk2(acc[p][0]);
        float2 v1 = unpk2(acc[p][1]);
        float2 v2 = unpk2(acc[p][2]);
        float2 v3 = unpk2(acc[p][3]);
        size_t a0 = base + (size_t)(rbase + 2 * p) * rowstride;
        size_t a1 = a0 + rowstride;
        out[a0 + lane] = v0.x; out[a0 + lane + 32] = v1.x;
        out[a0 + lane + 64] = v2.x; out[a0 + lane + 96] = v3.x;
        out[a1 + lane] = v0.y; out[a1 + lane + 32] = v1.y;
        out[a1 + lane + 64] = v2.y; out[a1 + lane + 96] = v3.y;
        float sl0x = wred(v0.x * al0 + v1.x * al1);
        float sl1x = wred(v2.x * al2v + v3.x * al3);
        float sr0x = wred(v0.x * ar0 + v1.x * ar1);
        float sr1x = wred(v2.x * ar2v + v3.x * ar3);
        float sl0y = wred(v0.y * al0 + v1.y * al1);
        float sl1y = wred(v2.y * al2v + v3.y * al3);
        float sr0y = wred(v0.y * ar0 + v1.y * ar1);
        float sr1y = wred(v2.y * ar2v + v3.y * ar3);
        if (lane == 0) {
            size_t rA = m0 + rbase + 2 * p;
            el[rA * 2 + 0] = sl0x; el[rA * 2 + 1] = sl1x;
            er[rA * 2 + 0] = sr0x; er[rA * 2 + 1] = sr1x;
            el[(rA + 1) * 2 + 0] = sl0y; el[(rA + 1) * 2 + 1] = sl1y;
            er[(rA + 1) * 2 + 0] = sr0y; er[(rA + 1) * 2 + 1] = sr1y;
        }
    }
}

// ---------------- gemm2/3: 16 rows/warp, 128 rows/block (R8 variant) ----------------
template <int CO, bool ELR, bool LNIN, int TIN>
__global__ __launch_bounds__(256) void k_gemm(
        const float* __restrict__ in, const float* __restrict__ wp,
        const float* __restrict__ bias, float* __restrict__ out,
        const float* __restrict__ al, const float* __restrict__ ar,
        float* __restrict__ el, float* __restrict__ er,
        const float* __restrict__ lnw, const float* __restrict__ lnb,
        const double* __restrict__ stat) {
    const int CPT = CO / 32;
    size_t m0 = (size_t)blockIdx.x * 128;
    int tid = threadIdx.x;
    int warp = tid >> 5, lane = tid & 31;
    __shared__ __align__(16) float xs[64 * 128];
    __shared__ float mu_s, rs_s;
    if (LNIN) {
        if (tid == 0) ln_combine(stat, (int)(m0 >> 11), mu_s, rs_s);
        __syncthreads();
    }
    float mu = LNIN ? mu_s : 0.f, rs = LNIN ? rs_s : 1.f;
    for (int i = tid; i < 128 * 64; i += 256) {
        int r = i >> 6, k = i & 63;
        float v = in[m0 * 64 + i];
        if (LNIN) {
            int n = (int)((m0 + r) & 2047);
            v = (v - mu) * rs * lnw[n * 64 + k] + lnb[n * 64 + k];
        }
        xs[k * 128 + r] = v;
    }
    __syncthreads();
    int rbase = warp * 16;
    ull acc[8][CPT];
#pragma unroll
    for (int p = 0; p < 8; p++)
#pragma unroll
        for (int j = 0; j < CPT; j++) acc[p][j] = 0ull;
#pragma unroll 4
    for (int k = 0; k < 64; k++) {
        ull xv[8];
        const float* xp = &xs[k * 128 + rbase];
        lds128(xv[0], xv[1], xp);
        lds128(xv[2], xv[3], xp + 4);
        lds128(xv[4], xv[5], xp + 8);
        lds128(xv[6], xv[7], xp + 12);
        ull wd[CPT];
        if (CPT == 4) {
            float4 w4 = *(const float4*)&wp[(k * 32 + lane) * 4];
            wd[0] = dup2(w4.x); wd[1] = dup2(w4.y); wd[2] = dup2(w4.z); wd[3] = dup2(w4.w);
        } else {
            float2 w2 = *(const float2*)&wp[(k * 32 + lane) * 2];
            wd[0] = dup2(w2.x); wd[1] = dup2(w2.y);
        }
#pragma unroll
        for (int p = 0; p < 8; p++)
#pragma unroll
            for (int j = 0; j < CPT; j++) fma2(acc[p][j], xv[p], wd[j]);
    }
    if (ELR) {
        const size_t rowstride = (size_t)8 * TIN * 128;
        size_t base = (size_t)(m0 & 2047) * rowstride + (size_t)(m0 >> 11) * 128;
        float al0 = al[lane], al1 = al[lane + 32], al2v = al[lane + 64], al3 = al[lane + 96];
        float ar0 = ar[lane], ar1 = ar[lane + 32], ar2v = ar[lane + 64], ar3 = ar[lane + 96];
#pragma unroll
        for (int p = 0; p < 8; p++) {
            float2 v0 = unpk2(acc[p][0]);
            float2 v1 = unpk2(acc[p][1]);
            float2 v2 = unpk2(acc[p][2]);
            float2 v3 = unpk2(acc[p][3]);
            size_t a0 = base + (size_t)(rbase + 2 * p) * rowstride;
            size_t a1 = a0 + rowstride;
            out[a0 + lane] = v0.x; out[a0 + lane + 32] = v1.x;
            out[a0 + lane + 64] = v2.x; out[a0 + lane + 96] = v3.x;
            out[a1 + lane] = v0.y; out[a1 + lane + 32] = v1.y;
            out[a1 + lane + 64] = v2.y; out[a1 + lane + 96] = v3.y;
            float sl0x = wred(v0.x * al0 + v1.x * al1);
            float sl1x = wred(v2.x * al2v + v3.x * al3);
            float sr0x = wred(v0.x * ar0 + v1.x * ar1);
            float sr1x = wred(v2.x * ar2v + v3.x * ar3);
            float sl0y = wred(v0.y * al0 + v1.y * al1);
            float sl1y = wred(v2.y * al2v + v3.y * al3);
            float sr0y = wred(v0.y * ar0 + v1.y * ar1);
            float sr1y = wred(v2.y * ar2v + v3.y * ar3);
            if (lane == 0) {
                size_t rA = m0 + rbase + 2 * p;
                el[rA * 2 + 0] = sl0x; el[rA * 2 + 1] = sl1x;
                er[rA * 2 + 0] = sr0x; er[rA * 2 + 1] = sr1x;
                el[(rA + 1) * 2 + 0] = sl0y; el[(rA + 1) * 2 + 1] = sl1y;
                er[(rA + 1) * 2 + 0] = sr0y; er[(rA + 1) * 2 + 1] = sr1y;
            }
        }
    } else {
        float bv0 = bias[lane], bv1 = bias[lane + 32];
#pragma unroll
        for (int p = 0; p < 8; p++) {
            float2 v0 = unpk2(acc[p][0]);
            float2 v1 = unpk2(acc[p][1]);
            size_t r0 = m0 + rbase + 2 * p;
            out[r0 * 64 + lane] = v0.x + bv0;
            out[r0 * 64 + lane + 32] = v1.x + bv1;
            out[(r0 + 1) * 64 + lane] = v0.y + bv0;
            out[(r0 + 1) * 64 + lane + 32] = v1.y + bv1;
        }
    }
}

// ---------------- edge softmax alpha: [e][b][2*TIN] ----------------
template <int TIN>
__global__ void k_alpha(const float* __restrict__ el, const float* __restrict__ er,
                        const int* __restrict__ rowptr, const int* __restrict__ col,
                        float* __restrict__ alpha) {
    const int STR = 2 * TIN;
    int gw = blockIdx.x * 8 + (threadIdx.x >> 5);
    int n = gw >> 3, b = gw & 7;
    int lane = threadIdx.x & 31;
    int r0 = rowptr[n], deg = rowptr[n + 1] - r0;
    const float2* el2 = (const float2*)el;
    const float2* er2 = (const float2*)er;
    if (deg <= 32) {
        int s = (lane < deg) ? col[r0 + lane] : 0;
        float av[STR];
        for (int t = 0; t < TIN; t++) {
            int base = (b * TIN + t) * 2048;
            float2 erd = er2[base + n];
            float2 ela = (lane < deg) ? el2[base + s] : make_float2(-3.0e38f, -3.0e38f);
#pragma unroll
            for (int h = 0; h < 2; h++) {
                float v = (h ? ela.y + erd.y : ela.x + erd.x);
                float e = (lane < deg) ? (v > 0.f ? v : 0.2f * v) : -3.0e38f;
                float mx = e;
                for (int o = 16; o; o >>= 1) mx = fmaxf(mx, __shfl_xor_sync(0xFFFFFFFFu, mx, o));
                float a = (lane < deg) ? __expf(e - mx) : 0.f;
                float sm = a;
                for (int o = 16; o; o >>= 1) sm += __shfl_xor_sync(0xFFFFFFFFu, sm, o);
                av[t * 2 + h] = a / sm;
            }
        }
        if (lane < deg) {
            float4* ap = (float4*)&alpha[((size_t)(r0 + lane) * 8 + b) * STR];
#pragma unroll
            for (int q = 0; q < STR / 4; q++) ap[q] = ((float4*)av)[q];
        }
    } else {
        for (int t = 0; t < TIN; t++) {
            int base = (b * TIN + t) * 2048;
            for (int h = 0; h < 2; h++) {
                float erd = er[(size_t)(base + n) * 2 + h];
                float mx = -3.0e38f;
                for (int j = lane; j < deg; j += 32) {
                    float v = el[(size_t)(base + col[r0 + j]) * 2 + h] + erd;
                    v = v > 0.f ? v : 0.2f * v;
                    mx = fmaxf(mx, v);
                }
                for (int o = 16; o; o >>= 1) mx = fmaxf(mx, __shfl_xor_sync(0xFFFFFFFFu, mx, o));
                float sm = 0.f;
                for (int j = lane; j < deg; j += 32) {
                    float v = el[(size_t)(base + col[r0 + j]) * 2 + h] + erd;
                    v = v > 0.f ? v : 0.2f * v;
                    sm += __expf(v - mx);
                }
                for (int o = 16; o; o >>= 1) sm += __shfl_xor_sync(0xFFFFFFFFu, sm, o);
                for (int j = lane; j < deg; j += 32) {
                    float v = el[(size_t)(base + col[r0 + j]) * 2 + h] + erd;
                    v = v > 0.f ? v : 0.2f * v;
                    alpha[((size_t)(r0 + j) * 8 + b) * STR + t * 2 + h] = __expf(v - mx) / sm;
                }
            }
        }
    }
}

// ---------------- gather ----------------
template <int TIN>
__global__ void k_gather(const float* __restrict__ feat, const float* __restrict__ alpha,
                         const int* __restrict__ rowptr, const int* __restrict__ col,
                         const float* __restrict__ bias, float* __restrict__ y) {
    const int STR = 2 * TIN;
    int n = blockIdx.x, b = blockIdx.y;
    int c = threadIdx.x;  // 64
    int r0 = rowptr[n], deg = rowptr[n + 1] - r0;
    float acc[STR];
#pragma unroll
    for (int i = 0; i < STR; i++) acc[i] = 0.f;
    for (int j = 0; j < deg; j++) {
        int s = col[r0 + j];
        float av[STR];
        const float4* ap = (const float4*)&alpha[((size_t)(r0 + j) * 8 + b) * STR];
#pragma unroll
        for (int q = 0; q < STR / 4; q++) ((float4*)av)[q] = ap[q];
        const float* fp = feat + ((size_t)s * 8 + b) * (TIN * 128) + c;
#pragma unroll
        for (int t = 0; t < TIN; t++) {
#pragma unroll
            for (int h = 0; h < 2; h++)
                acc[t * 2 + h] += av[t * 2 + h] * fp[t * 128 + h * 64];
        }
    }
#pragma unroll
    for (int t = 0; t < TIN; t++) {
#pragma unroll
        for (int h = 0; h < 2; h++) {
            float v = acc[t * 2 + h] + bias[h * 64 + c];
            v = v > 0.f ? v : 0.f;
            y[((size_t)(b * 2 * TIN + t * 2 + h) * 2048 + n) * 64 + c] = v;
        }
    }
}

// ---------------- conv1: plain-tf32 wmma, LN2 fused (R10 version, measured good) ----------------
__global__ __launch_bounds__(256) void k_conv1(
        const float* __restrict__ z, const float* __restrict__ wtm,
        const float* __restrict__ tb1, float* __restrict__ o1,
        const float* __restrict__ lnw, const float* __restrict__ lnb,
        const double* __restrict__ stat) {
    int b = blockIdx.x >> 8;
    int nt = blockIdx.x & 255;
    int n0 = nt * 8;
    __shared__ __align__(16) float abuf[96 * 72];
    __shared__ float muv[16], rsv[16];
    if (threadIdx.x < 16)
        ln_combine(stat, b * 16 + threadIdx.x, muv[threadIdx.x], rsv[threadIdx.x]);
    int w = threadIdx.x >> 5;
    int nw = w & 3;
    int mw0 = w >> 2;
    wmma::fragment<wmma::accumulator, 16, 16, 8, float> cfrag[3];
#pragma unroll
    for (int i = 0; i < 3; i++) wmma::fill_fragment(cfrag[i], 0.f);
    for (int k = 0; k < 5; k++) {
        __syncthreads();
        for (int i = threadIdx.x; i < 96 * 64; i += 256) {
            int r = i >> 6, ci = i & 63;
            int j = r >> 3, nn = r & 7;
            int t = j + k;
            float v = z[((size_t)((b * 16 + t) * 2048 + n0 + nn)) * 64 + ci];
            v = (v - muv[t]) * rsv[t] * lnw[(n0 + nn) * 64 + ci] + lnb[(n0 + nn) * 64 + ci];
            abuf[r * 72 + ci] = v;
        }
        __syncthreads();
#pragma unroll
        for (int kk = 0; kk < 8; kk++) {
            wmma::fragment<wmma::matrix_b, 16, 16, 8, wmma::precision::tf32, wmma::row_major> bfrag;
            wmma::load_matrix_sync(bfrag, wtm + (size_t)(k * 64 + kk * 8) * 64 + nw * 16, 64);
#pragma unroll
            for (int t2 = 0; t2 < bfrag.num_elements; t2++)
                bfrag.x[t2] = wmma::__float_to_tf32(bfrag.x[t2]);
#pragma unroll
            for (int i = 0; i < 3; i++) {
                int mw = mw0 + 2 * i;
                wmma::fragment<wmma::matrix_a, 16, 16, 8, wmma::precision::tf32, wmma::row_major> afrag;
                wmma::load_matrix_sync(afrag, abuf + mw * 16 * 72 + kk * 8, 72);
#pragma unroll
                for (int t2 = 0; t2 < afrag.num_elements; t2++)
                    afrag.x[t2] = wmma::__float_to_tf32(afrag.x[t2]);
                wmma::mma_sync(cfrag[i], afrag, bfrag, cfrag[i]);
            }
        }
    }
    __syncthreads();
#pragma unroll
    for (int i = 0; i < 3; i++) {
        int mw = mw0 + 2 * i;
        wmma::store_matrix_sync(abuf + mw * 16 * 72 + nw * 16, cfrag[i], 72, wmma::mem_row_major);
    }
    __syncthreads();
    for (int i = threadIdx.x; i < 96 * 64; i += 256) {
        int r = i >> 6, co = i & 63;
        int j = r >> 3, nn = r & 7;
        o1[((size_t)((b * 12 + j) * 2048 + n0 + nn)) * 64 + co] = abuf[r * 72 + co] + tb1[co];
    }
}

// ---------------- final FC (scrambled reshape fused) ----------------
__global__ void k_fc(const float* __restrict__ o2, const float* __restrict__ fw,
                     const float* __restrict__ fb, float* __restrict__ out) {
    int b = blockIdx.x >> 5, q = blockIdx.x & 31;
    __shared__ float s[64 * 64];
    int c = threadIdx.x & 63;
    int rb = threadIdx.x >> 6;
    float acc[3] = {0.f, 0.f, 0.f};
    for (int j = 0; j < 12; j++) {
        __syncthreads();
        for (int i = threadIdx.x; i < 4096; i += 256)
            s[i] = o2[((size_t)((b * 12 + j) * 2048 + q * 64)) * 64 + i];
        __syncthreads();
        for (int rn = 0; rn < 64; rn++) {
            float v = s[rn * 64 + c];
#pragma unroll
            for (int rr = 0; rr < 3; rr++)
                acc[rr] += v * fw[(rb * 3 + rr) * 768 + rn * 12 + j];
        }
    }
    int np = 32 * c + q;
#pragma unroll
    for (int rr = 0; rr < 3; rr++) {
        int r = rb * 3 + rr;
        out[((size_t)b * 2048 + np) * 12 + r] = acc[rr] + fb[r];
    }
}

// ---------------- host ----------------
static void* sym(const void* s) {
    void* p = nullptr;
    cudaGetSymbolAddress(&p, s);
    return p;
}

extern "C" void kernel_launch(void* const* d_in, const int* in_sizes, int n_in,
                              void* d_out, int out_size) {
    const float* x = (const float*)d_in[0];
    const int* src = (const int*)d_in[1];
    const int* dst = (const int*)d_in[2];
    const float* W1 = (const float*)d_in[3];
    const float* al1 = (const float*)d_in[4];
    const float* ar1 = (const float*)d_in[5];
    const float* b1 = (const float*)d_in[6];
    const float* W2 = (const float*)d_in[7];
    const float* al2 = (const float*)d_in[8];
    const float* ar2 = (const float*)d_in[9];
    const float* b2 = (const float*)d_in[10];
    const float* ln1w = (const float*)d_in[11];
    const float* ln1b = (const float*)d_in[12];
    const float* ln2w = (const float*)d_in[13];
    const float* ln2b = (const float*)d_in[14];
    const float* tc1w = (const float*)d_in[15];
    const float* tc1b = (const float*)d_in[16];
    const float* ln3w = (const float*)d_in[17];
    const float* ln3b = (const float*)d_in[18];
    const float* tc2w = (const float*)d_in[19];
    const float* tc2b = (const float*)d_in[20];
    const float* fcw = (const float*)d_in[21];
    const float* fcb = (const float*)d_in[22];
    int E = in_sizes[1];

    float* xT = (float*)sym(g_xT);
    float* feat = (float*)sym(g_feat);
    float* el = (float*)sym(g_el);
    float* er = (float*)sym(g_er);
    float* alpha = (float*)sym(g_alpha);
    float* y = (float*)sym(g_y);
    float* z = (float*)sym(g_z);
    float* o1 = (float*)sym(g_o1);
    float* o2 = (float*)sym(g_o2);
    float* wtm = (float*)sym(g_wtm);
    float* wp1 = (float*)sym(g_wp1);
    float* wp2 = (float*)sym(g_wp2);
    float* wpt2 = (float*)sym(g_wpt2);
    double* stat = (double*)sym(g_stat);
    int* deg = (int*)sym(g_deg);
    int* cursor = (int*)sym(g_cursor);
    int* rowptr = (int*)sym(g_rowptr);
    int* col = (int*)sym(g_col);
    float* out = (float*)d_out;

    // slots 1-3 setup so capture slot #4 = gemm1
    k_transpose_x<<<16384, 256>>>(x, xT, deg);                         // 1
    k_count<<<(E + 255) / 256, 256>>>(dst, deg, E);                    // 2
    k_packw128<<<32, 256>>>(W1, wp1);                                  // 3
    k_gemm8<4><<<1024, 256>>>(xT, wp1, feat, al1, ar1, el, er);        // 4 <- ncu capture
    k_scan<<<1, 1024>>>(deg, rowptr, cursor);                          // 5
    k_fill_atomic<<<(E + 255) / 256, 256>>>(dst, src, cursor, col, E); // 6
    k_sortcol<<<8, 256>>>(rowptr, col);                                // 7
    k_packw128<<<32, 256>>>(W2, wp2);                                  // 8

    // ---- GAT layer 1 ----
    k_alpha<4><<<2048, 256>>>(el, er, rowptr, col, alpha);
    {
        dim3 g(2048, 8);
        k_gather<4><<<g, 64>>>(feat, alpha, rowptr, col, b1, y);
    }
    k_lnpart<<<256, 1024>>>(y, stat);

    // ---- GAT layer 2 (LN1 fused into GEMM input) ----
    k_gemm<128, true, true, 8><<<1024, 256>>>(y, wp2, nullptr, feat, al2, ar2, el, er,
                                              ln1w, ln1b, stat);
    k_alpha<8><<<2048, 256>>>(el, er, rowptr, col, alpha);
    {
        dim3 g(2048, 8);
        k_gather<8><<<g, 64>>>(feat, alpha, rowptr, col, b2, z);
    }
    k_lnpart<<<512, 1024>>>(z, stat);

    // ---- output layer ----
    k_twm<<<80, 256>>>(tc1w, wtm);
    k_packw64<<<16, 256>>>(tc2w, wpt2);
    k_conv1<<<2048, 256>>>(z, wtm, tc1b, o1, ln2w, ln2b, stat);  // LN2 fused, plain tf32 wmma
    k_lnpart<<<384, 1024>>>(o1, stat);
    k_gemm<64, false, true, 0><<<1536, 256>>>(o1, wpt2, tc2b, o2, nullptr, nullptr, nullptr,
                                              nullptr, ln3w, ln3b, stat);  // LN3 fused
    k_fc<<<256, 256>>>(o2, fcw, fcb, out);
}

// round 15
// speedup vs baseline: 1.3963x; 1.1094x over previous
#include <cuda_runtime.h>
#include <cuda_bf16.h>
#include <mma.h>
#include <math.h>

using namespace nvcuda;

#define NN_ 2048
#define BB_ 8

typedef unsigned long long ull;

__device__ __forceinline__ ull pk2(float x, float y) {
    ull r; asm("mov.b64 %0,{%1,%2};" : "=l"(r) : "f"(x), "f"(y)); return r;
}
__device__ __forceinline__ ull dup2(float x) { return pk2(x, x); }
__device__ __forceinline__ void fma2(ull& d, ull a, ull b) {
    asm("fma.rn.f32x2 %0,%1,%2,%0;" : "+l"(d) : "l"(a), "l"(b));
}
__device__ __forceinline__ float2 unpk2(ull v) {
    float2 f; asm("mov.b64 {%0,%1},%2;" : "=f"(f.x), "=f"(f.y) : "l"(v)); return f;
}
__device__ __forceinline__ void lds128(ull& a, ull& b, const float* p) {
    unsigned addr = (unsigned)__cvta_generic_to_shared((void*)p);
    asm("ld.shared.v2.b64 {%0,%1},[%2];" : "=l"(a), "=l"(b) : "r"(addr));
}
__device__ __forceinline__ float wred(float v) {
#pragma unroll
    for (int o = 16; o; o >>= 1) v += __shfl_xor_sync(0xFFFFFFFFu, v, o);
    return v;
}

// ---------------- scratch ----------------
__device__ float g_xT[4194304];      // [B,4,N,C]
__device__ float g_feat[16777216];   // node-major [n][b][t][128]
__device__ float g_el[262144];       // [b,t,n,2]
__device__ float g_er[262144];
__device__ float g_alpha[1310720];   // [e][b][2*TIN]
__device__ float g_y[16777216];      // [b,8,n,64]
__device__ float g_z[16777216];      // [b,16,n,64]
__device__ float g_o1[12582912];     // [b,12,n,64]
__device__ float g_o2[12582912];
__device__ float g_wtm[20480];       // conv1 weights [k*64+ci][co]
__device__ float g_wp1[8192];        // W1 packed [k][lane32][4]
__device__ double g_stat[1024];
__device__ int   g_deg[2048];
__device__ int   g_cursor[2048];
__device__ int   g_rowptr[2049];
__device__ int   g_col[16384];

// ---------------- transpose x (+ zero deg) ----------------
__global__ void k_transpose_x(const float* __restrict__ x, float* __restrict__ xT,
                              int* __restrict__ deg) {
    int i = blockIdx.x * 256 + threadIdx.x;
    if (i < 2048) deg[i] = 0;
    if (i >= BB_ * NN_ * 4 * 64) return;
    int c = i & 63;
    int t = (i >> 6) & 3;
    int n = (i >> 8) & 2047;
    int b = i >> 19;
    xT[((size_t)(b * 4 + t) * 2048 + n) * 64 + c] = x[i];
}

// ---------------- CSR build ----------------
__global__ void k_count(const int* __restrict__ dst, int* __restrict__ deg, int E) {
    int e = blockIdx.x * 256 + threadIdx.x;
    if (e < E) atomicAdd(&deg[dst[e]], 1);
}

__global__ void k_scan(const int* __restrict__ deg, int* __restrict__ rowptr,
                       int* __restrict__ cursor) {
    __shared__ int s[2048];
    int tid = threadIdx.x;
    s[tid] = deg[tid];
    s[tid + 1024] = deg[tid + 1024];
    __syncthreads();
    for (int off = 1; off < 2048; off <<= 1) {
        int i0 = tid, i1 = tid + 1024;
        int a0 = (i0 >= off) ? s[i0 - off] : 0;
        int a1 = (i1 >= off) ? s[i1 - off] : 0;
        __syncthreads();
        s[i0] += a0; s[i1] += a1;
        __syncthreads();
    }
    rowptr[tid + 1] = s[tid];
    rowptr[tid + 1025] = s[tid + 1024];
    if (tid == 0) { rowptr[0] = 0; cursor[0] = 0; }
    if (tid < 1023) cursor[tid + 1] = s[tid];
    cursor[tid + 1024] = s[tid + 1023];
}

__global__ void k_fill_atomic(const int* __restrict__ dst, const int* __restrict__ src,
                              int* __restrict__ cursor, int* __restrict__ col, int E) {
    int e = blockIdx.x * 256 + threadIdx.x;
    if (e >= E) return;
    int pos = atomicAdd(&cursor[dst[e]], 1);
    col[pos] = src[e];
}

__global__ void k_sortcol(const int* __restrict__ rowptr, int* __restrict__ col) {
    int n = blockIdx.x * 256 + threadIdx.x;
    if (n >= NN_) return;
    int r0 = rowptr[n], r1 = rowptr[n + 1];
    for (int i = r0 + 1; i < r1; i++) {
        int v = col[i];
        int j = i - 1;
        while (j >= r0 && col[j] > v) { col[j + 1] = col[j]; j--; }
        col[j + 1] = v;
    }
}

// ---------------- weight prep ----------------
__global__ void k_twm(const float* __restrict__ w, float* __restrict__ wtm) {
    int i = blockIdx.x * 256 + threadIdx.x;
    if (i >= 20480) return;
    int co = i & 63;
    int ci = (i >> 6) & 63;
    int k = i >> 12;
    wtm[(k * 64 + ci) * 64 + co] = w[(co * 64 + ci) * 5 + k];
}

__global__ void k_packw128(const float* __restrict__ w, float* __restrict__ wp) {
    int i = blockIdx.x * 256 + threadIdx.x;
    if (i >= 8192) return;
    int k = i >> 7, rem = i & 127, j = rem >> 5, lane = rem & 31;
    wp[(k * 32 + lane) * 4 + j] = w[i];
}

// ---------------- LN partial stats ----------------
__global__ void k_lnpart(const float* __restrict__ x, double* __restrict__ stat) {
    int slice = blockIdx.x >> 2, q = blockIdx.x & 3;
    const float* xs = x + (size_t)slice * 131072 + q * 32768;
    double s1 = 0.0, s2 = 0.0;
    for (int i = threadIdx.x; i < 32768; i += 1024) {
        float v = xs[i];
        s1 += v;
        s2 += (double)v * (double)v;
    }
    for (int o = 16; o; o >>= 1) {
        s1 += __shfl_xor_sync(0xFFFFFFFFu, s1, o);
        s2 += __shfl_xor_sync(0xFFFFFFFFu, s2, o);
    }
    __shared__ double sh1[32], sh2[32];
    int wid = threadIdx.x >> 5, lane = threadIdx.x & 31;
    if (!lane) { sh1[wid] = s1; sh2[wid] = s2; }
    __syncthreads();
    if (threadIdx.x == 0) {
        double t1 = 0, t2 = 0;
        for (int k = 0; k < 32; k++) { t1 += sh1[k]; t2 += sh2[k]; }
        stat[slice * 8 + q * 2] = t1;
        stat[slice * 8 + q * 2 + 1] = t2;
    }
}

__device__ __forceinline__ void ln_combine(const double* __restrict__ stat, int slice,
                                           float& mu, float& rs) {
    double t1 = 0, t2 = 0;
#pragma unroll
    for (int q = 0; q < 4; q++) {
        t1 += stat[slice * 8 + q * 2];
        t2 += stat[slice * 8 + q * 2 + 1];
    }
    double m = t1 / 131072.0;
    double var = t2 / 131072.0 - m * m;
    mu = (float)m;
    rs = (float)rsqrt(var + 1e-5);
}

// ---------------- gemm1: 8 rows/warp f32x2 (R9/R13 variant, measured) ----------------
template <int TIN>
__global__ __launch_bounds__(256, 3) void k_gemm8(
        const float* __restrict__ in, const float* __restrict__ wp,
        float* __restrict__ out, const float* __restrict__ al, const float* __restrict__ ar,
        float* __restrict__ el, float* __restrict__ er) {
    size_t m0 = (size_t)blockIdx.x * 64;
    int tid = threadIdx.x;
    int warp = tid >> 5, lane = tid & 31;
    __shared__ __align__(16) float xs[64 * 64];
    for (int i = tid; i < 64 * 64; i += 256) {
        int r = i >> 6, k = i & 63;
        xs[k * 64 + r] = in[m0 * 64 + i];
    }
    __syncthreads();
    int rbase = warp * 8;
    ull acc[4][4];
#pragma unroll
    for (int p = 0; p < 4; p++)
#pragma unroll
        for (int j = 0; j < 4; j++) acc[p][j] = 0ull;
#pragma unroll 8
    for (int k = 0; k < 64; k++) {
        ull xv[4];
        const float* xp = &xs[k * 64 + rbase];
        lds128(xv[0], xv[1], xp);
        lds128(xv[2], xv[3], xp + 4);
        float4 w4 = *(const float4*)&wp[(k * 32 + lane) * 4];
        ull wd[4] = {dup2(w4.x), dup2(w4.y), dup2(w4.z), dup2(w4.w)};
#pragma unroll
        for (int p = 0; p < 4; p++)
#pragma unroll
            for (int j = 0; j < 4; j++) fma2(acc[p][j], xv[p], wd[j]);
    }
    const size_t rowstride = (size_t)8 * TIN * 128;
    size_t base = (size_t)(m0 & 2047) * rowstride + (size_t)(m0 >> 11) * 128;
    float al0 = al[lane], al1 = al[lane + 32], al2v = al[lane + 64], al3 = al[lane + 96];
    float ar0 = ar[lane], ar1 = ar[lane + 32], ar2v = ar[lane + 64], ar3 = ar[lane + 96];
#pragma unroll
    for (int p = 0; p < 4; p++) {
        float2 v0 = unpk2(acc[p][0]);
        float2 v1 = unpk2(acc[p][1]);
        float2 v2 = unpk2(acc[p][2]);
        float2 v3 = unpk2(acc[p][3]);
        size_t a0 = base + (size_t)(rbase + 2 * p) * rowstride;
        size_t a1 = a0 + rowstride;
        out[a0 + lane] = v0.x; out[a0 + lane + 32] = v1.x;
        out[a0 + lane + 64] = v2.x; out[a0 + lane + 96] = v3.x;
        out[a1 + lane] = v0.y; out[a1 + lane + 32] = v1.y;
        out[a1 + lane + 64] = v2.y; out[a1 + lane + 96] = v3.y;
        float sl0x = wred(v0.x * al0 + v1.x * al1);
        float sl1x = wred(v2.x * al2v + v3.x * al3);
        float sr0x = wred(v0.x * ar0 + v1.x * ar1);
        float sr1x = wred(v2.x * ar2v + v3.x * ar3);
        float sl0y = wred(v0.y * al0 + v1.y * al1);
        float sl1y = wred(v2.y * al2v + v3.y * al3);
        float sr0y = wred(v0.y * ar0 + v1.y * ar1);
        float sr1y = wred(v2.y * ar2v + v3.y * ar3);
        if (lane == 0) {
            size_t rA = m0 + rbase + 2 * p;
            el[rA * 2 + 0] = sl0x; el[rA * 2 + 1] = sl1x;
            er[rA * 2 + 0] = sr0x; er[rA * 2 + 1] = sr1x;
            el[(rA + 1) * 2 + 0] = sl0y; el[(rA + 1) * 2 + 1] = sl1y;
            er[(rA + 1) * 2 + 0] = sr0y; er[(rA + 1) * 2 + 1] = sr1y;
        }
    }
}

// ---------------- gemm2: tf32 wmma transposed (C^T = W^T x act^T), LN1 fused ----------------
// Block: 256 thr / 8 warps; warp w owns co-tile w (16 cols). 128 rows/block.
// A frag (weights) loaded ONCE per warp; B (activations) from smem staging.
__global__ __launch_bounds__(256) void k_wgemm2t(
        const float* __restrict__ in, const float* __restrict__ W2,
        float* __restrict__ feat,
        const float* __restrict__ lnw, const float* __restrict__ lnb,
        const double* __restrict__ stat) {
    const int TIN = 8;
    size_t m0 = (size_t)blockIdx.x * 128;
    int tid = threadIdx.x;
    int w = tid >> 5;
    __shared__ __align__(16) float xs[128 * 72];   // [row][k], ld=72
    float mu, rs;
    ln_combine(stat, (int)(m0 >> 11), mu, rs);
    for (int i = tid; i < 128 * 64; i += 256) {
        int r = i >> 6, k = i & 63;
        int n = (int)((m0 + r) & 2047);
        float v = in[m0 * 64 + i];
        xs[r * 72 + k] = (v - mu) * rs * lnw[n * 64 + k] + lnb[n * 64 + k];
    }
    // preload weight fragments: A = W^T[co 16][k 8] = col_major view of W2 (ld=128)
    wmma::fragment<wmma::matrix_a, 16, 16, 8, wmma::precision::tf32, wmma::col_major> af[8];
#pragma unroll
    for (int kk = 0; kk < 8; kk++) {
        wmma::load_matrix_sync(af[kk], W2 + (size_t)(kk * 8) * 128 + w * 16, 128);
#pragma unroll
        for (int t2 = 0; t2 < af[kk].num_elements; t2++)
            af[kk].x[t2] = wmma::__float_to_tf32(af[kk].x[t2]);
    }
    __syncthreads();
    const size_t rowstride = (size_t)8 * TIN * 128;  // 8192
    size_t fbase = (size_t)(m0 & 2047) * rowstride + (size_t)(m0 >> 11) * 128 + w * 16;
#pragma unroll 2
    for (int rt = 0; rt < 8; rt++) {
        wmma::fragment<wmma::accumulator, 16, 16, 8, float> cf;
        wmma::fill_fragment(cf, 0.f);
#pragma unroll
        for (int kk = 0; kk < 8; kk++) {
            // B = act^T[k 8][row 16]: col_major over xs (ld=72)
            wmma::fragment<wmma::matrix_b, 16, 16, 8, wmma::precision::tf32, wmma::col_major> bf;
            wmma::load_matrix_sync(bf, xs + (rt * 16) * 72 + kk * 8, 72);
#pragma unroll
            for (int t2 = 0; t2 < bf.num_elements; t2++)
                bf.x[t2] = wmma::__float_to_tf32(bf.x[t2]);
            wmma::mma_sync(cf, af[kk], bf, cf);
        }
        // C^T(co,row) -> feat[(n+row)*8192 + bt*128 + co0 + co] : col_major store, ld=8192
        wmma::store_matrix_sync(feat + fbase + (size_t)(rt * 16) * rowstride, cf,
                                rowstride, wmma::mem_col_major);
    }
}

// ---------------- el/er from feat (TIN=8): one warp per row (R11-verified) ----------------
__global__ void k_elr2(const float* __restrict__ feat, const float* __restrict__ al,
                       const float* __restrict__ ar, float* __restrict__ el,
                       float* __restrict__ er) {
    int r = blockIdx.x * 8 + (threadIdx.x >> 5);
    int lane = threadIdx.x & 31;
    int n = r & 2047, bt = r >> 11;
    const float* f = feat + (size_t)n * 8192 + bt * 128;
    float f0 = f[lane], f1 = f[lane + 32], f2 = f[lane + 64], f3 = f[lane + 96];
    float e0 = wred(f0 * al[lane] + f1 * al[lane + 32]);
    float e1 = wred(f2 * al[lane + 64] + f3 * al[lane + 96]);
    float r0 = wred(f0 * ar[lane] + f1 * ar[lane + 32]);
    float r1 = wred(f2 * ar[lane + 64] + f3 * ar[lane + 96]);
    if (lane == 0) {
        el[(size_t)r * 2 + 0] = e0; el[(size_t)r * 2 + 1] = e1;
        er[(size_t)r * 2 + 0] = r0; er[(size_t)r * 2 + 1] = r1;
    }
}

// ---------------- gemm3: tf32 wmma transposed, LN3 fused, bias deferred to fc ----------------
// warp w: co-tile (w&3), row-half (w>>2) -> rt in [half*4, half*4+4)
__global__ __launch_bounds__(256) void k_wgemm3t(
        const float* __restrict__ in, const float* __restrict__ tc2w,
        float* __restrict__ out,
        const float* __restrict__ lnw, const float* __restrict__ lnb,
        const double* __restrict__ stat) {
    size_t m0 = (size_t)blockIdx.x * 128;
    int tid = threadIdx.x;
    int w = tid >> 5;
    int cot = w & 3, half = w >> 2;
    __shared__ __align__(16) float xs[128 * 72];
    float mu, rs;
    ln_combine(stat, (int)(m0 >> 11), mu, rs);
    for (int i = tid; i < 128 * 64; i += 256) {
        int r = i >> 6, k = i & 63;
        int n = (int)((m0 + r) & 2047);
        float v = in[m0 * 64 + i];
        xs[r * 72 + k] = (v - mu) * rs * lnw[n * 64 + k] + lnb[n * 64 + k];
    }
    // A = W^T[co][k] = tc2w[co][ci] row-major directly (ld=64)
    wmma::fragment<wmma::matrix_a, 16, 16, 8, wmma::precision::tf32, wmma::row_major> af[8];
#pragma unroll
    for (int kk = 0; kk < 8; kk++) {
        wmma::load_matrix_sync(af[kk], tc2w + (size_t)(cot * 16) * 64 + kk * 8, 64);
#pragma unroll
        for (int t2 = 0; t2 < af[kk].num_elements; t2++)
            af[kk].x[t2] = wmma::__float_to_tf32(af[kk].x[t2]);
    }
    __syncthreads();
#pragma unroll
    for (int q = 0; q < 4; q++) {
        int rt = half * 4 + q;
        wmma::fragment<wmma::accumulator, 16, 16, 8, float> cf;
        wmma::fill_fragment(cf, 0.f);
#pragma unroll
        for (int kk = 0; kk < 8; kk++) {
            wmma::fragment<wmma::matrix_b, 16, 16, 8, wmma::precision::tf32, wmma::col_major> bf;
            wmma::load_matrix_sync(bf, xs + (rt * 16) * 72 + kk * 8, 72);
#pragma unroll
            for (int t2 = 0; t2 < bf.num_elements; t2++)
                bf.x[t2] = wmma::__float_to_tf32(bf.x[t2]);
            wmma::mma_sync(cf, af[kk], bf, cf);
        }
        wmma::store_matrix_sync(out + (m0 + rt * 16) * 64 + cot * 16, cf, 64,
                                wmma::mem_col_major);
    }
}

// ---------------- edge softmax alpha: [e][b][2*TIN] ----------------
template <int TIN>
__global__ void k_alpha(const float* __restrict__ el, const float* __restrict__ er,
                        const int* __restrict__ rowptr, const int* __restrict__ col,
                        float* __restrict__ alpha) {
    const int STR = 2 * TIN;
    int gw = blockIdx.x * 8 + (threadIdx.x >> 5);
    int n = gw >> 3, b = gw & 7;
    int lane = threadIdx.x & 31;
    int r0 = rowptr[n], deg = rowptr[n + 1] - r0;
    const float2* el2 = (const float2*)el;
    const float2* er2 = (const float2*)er;
    if (deg <= 32) {
        int s = (lane < deg) ? col[r0 + lane] : 0;
        float av[STR];
        for (int t = 0; t < TIN; t++) {
            int base = (b * TIN + t) * 2048;
            float2 erd = er2[base + n];
            float2 ela = (lane < deg) ? el2[base + s] : make_float2(-3.0e38f, -3.0e38f);
#pragma unroll
            for (int h = 0; h < 2; h++) {
                float v = (h ? ela.y + erd.y : ela.x + erd.x);
                float e = (lane < deg) ? (v > 0.f ? v : 0.2f * v) : -3.0e38f;
                float mx = e;
                for (int o = 16; o; o >>= 1) mx = fmaxf(mx, __shfl_xor_sync(0xFFFFFFFFu, mx, o));
                float a = (lane < deg) ? __expf(e - mx) : 0.f;
                float sm = a;
                for (int o = 16; o; o >>= 1) sm += __shfl_xor_sync(0xFFFFFFFFu, sm, o);
                av[t * 2 + h] = a / sm;
            }
        }
        if (lane < deg) {
            float4* ap = (float4*)&alpha[((size_t)(r0 + lane) * 8 + b) * STR];
#pragma unroll
            for (int q = 0; q < STR / 4; q++) ap[q] = ((float4*)av)[q];
        }
    } else {
        for (int t = 0; t < TIN; t++) {
            int base = (b * TIN + t) * 2048;
            for (int h = 0; h < 2; h++) {
                float erd = er[(size_t)(base + n) * 2 + h];
                float mx = -3.0e38f;
                for (int j = lane; j < deg; j += 32) {
                    float v = el[(size_t)(base + col[r0 + j]) * 2 + h] + erd;
                    v = v > 0.f ? v : 0.2f * v;
                    mx = fmaxf(mx, v);
                }
                for (int o = 16; o; o >>= 1) mx = fmaxf(mx, __shfl_xor_sync(0xFFFFFFFFu, mx, o));
                float sm = 0.f;
                for (int j = lane; j < deg; j += 32) {
                    float v = el[(size_t)(base + col[r0 + j]) * 2 + h] + erd;
                    v = v > 0.f ? v : 0.2f * v;
                    sm += __expf(v - mx);
                }
                for (int o = 16; o; o >>= 1) sm += __shfl_xor_sync(0xFFFFFFFFu, sm, o);
                for (int j = lane; j < deg; j += 32) {
                    float v = el[(size_t)(base + col[r0 + j]) * 2 + h] + erd;
                    v = v > 0.f ? v : 0.2f * v;
                    alpha[((size_t)(r0 + j) * 8 + b) * STR + t * 2 + h] = __expf(v - mx) / sm;
                }
            }
        }
    }
}

// ---------------- gather ----------------
template <int TIN>
__global__ void k_gather(const float* __restrict__ feat, const float* __restrict__ alpha,
                         const int* __restrict__ rowptr, const int* __restrict__ col,
                         const float* __restrict__ bias, float* __restrict__ y) {
    const int STR = 2 * TIN;
    int n = blockIdx.x, b = blockIdx.y;
    int c = threadIdx.x;  // 64
    int r0 = rowptr[n], deg = rowptr[n + 1] - r0;
    float acc[STR];
#pragma unroll
    for (int i = 0; i < STR; i++) acc[i] = 0.f;
    for (int j = 0; j < deg; j++) {
        int s = col[r0 + j];
        float av[STR];
        const float4* ap = (const float4*)&alpha[((size_t)(r0 + j) * 8 + b) * STR];
#pragma unroll
        for (int q = 0; q < STR / 4; q++) ((float4*)av)[q] = ap[q];
        const float* fp = feat + ((size_t)s * 8 + b) * (TIN * 128) + c;
#pragma unroll
        for (int t = 0; t < TIN; t++) {
#pragma unroll
            for (int h = 0; h < 2; h++)
                acc[t * 2 + h] += av[t * 2 + h] * fp[t * 128 + h * 64];
        }
    }
#pragma unroll
    for (int t = 0; t < TIN; t++) {
#pragma unroll
        for (int h = 0; h < 2; h++) {
            float v = acc[t * 2 + h] + bias[h * 64 + c];
            v = v > 0.f ? v : 0.f;
            y[((size_t)(b * 2 * TIN + t * 2 + h) * 2048 + n) * 64 + c] = v;
        }
    }
}

// ---------------- conv1: plain-tf32 wmma, LN2 fused (R10/R13 verified) ----------------
__global__ __launch_bounds__(256) void k_conv1(
        const float* __restrict__ z, const float* __restrict__ wtm,
        const float* __restrict__ tb1, float* __restrict__ o1,
        const float* __restrict__ lnw, const float* __restrict__ lnb,
        const double* __restrict__ stat) {
    int b = blockIdx.x >> 8;
    int nt = blockIdx.x & 255;
    int n0 = nt * 8;
    __shared__ __align__(16) float abuf[96 * 72];
    __shared__ float muv[16], rsv[16];
    if (threadIdx.x < 16)
        ln_combine(stat, b * 16 + threadIdx.x, muv[threadIdx.x], rsv[threadIdx.x]);
    int w = threadIdx.x >> 5;
    int nw = w & 3;
    int mw0 = w >> 2;
    wmma::fragment<wmma::accumulator, 16, 16, 8, float> cfrag[3];
#pragma unroll
    for (int i = 0; i < 3; i++) wmma::fill_fragment(cfrag[i], 0.f);
    for (int k = 0; k < 5; k++) {
        __syncthreads();
        for (int i = threadIdx.x; i < 96 * 64; i += 256) {
            int r = i >> 6, ci = i & 63;
            int j = r >> 3, nn = r & 7;
            int t = j + k;
            float v = z[((size_t)((b * 16 + t) * 2048 + n0 + nn)) * 64 + ci];
            v = (v - muv[t]) * rsv[t] * lnw[(n0 + nn) * 64 + ci] + lnb[(n0 + nn) * 64 + ci];
            abuf[r * 72 + ci] = v;
        }
        __syncthreads();
#pragma unroll
        for (int kk = 0; kk < 8; kk++) {
            wmma::fragment<wmma::matrix_b, 16, 16, 8, wmma::precision::tf32, wmma::row_major> bfrag;
            wmma::load_matrix_sync(bfrag, wtm + (size_t)(k * 64 + kk * 8) * 64 + nw * 16, 64);
#pragma unroll
            for (int t2 = 0; t2 < bfrag.num_elements; t2++)
                bfrag.x[t2] = wmma::__float_to_tf32(bfrag.x[t2]);
#pragma unroll
            for (int i = 0; i < 3; i++) {
                int mw = mw0 + 2 * i;
                wmma::fragment<wmma::matrix_a, 16, 16, 8, wmma::precision::tf32, wmma::row_major> afrag;
                wmma::load_matrix_sync(afrag, abuf + mw * 16 * 72 + kk * 8, 72);
#pragma unroll
                for (int t2 = 0; t2 < afrag.num_elements; t2++)
                    afrag.x[t2] = wmma::__float_to_tf32(afrag.x[t2]);
                wmma::mma_sync(cfrag[i], afrag, bfrag, cfrag[i]);
            }
        }
    }
    __syncthreads();
#pragma unroll
    for (int i = 0; i < 3; i++) {
        int mw = mw0 + 2 * i;
        wmma::store_matrix_sync(abuf + mw * 16 * 72 + nw * 16, cfrag[i], 72, wmma::mem_row_major);
    }
    __syncthreads();
    for (int i = threadIdx.x; i < 96 * 64; i += 256) {
        int r = i >> 6, co = i & 63;
        int j = r >> 3, nn = r & 7;
        o1[((size_t)((b * 12 + j) * 2048 + n0 + nn)) * 64 + co] = abuf[r * 72 + co] + tb1[co];
    }
}

// ---------------- final FC (scrambled reshape + tc2 bias fused; R11-verified) ----------------
__global__ void k_fc(const float* __restrict__ o2, const float* __restrict__ tb2,
                     const float* __restrict__ fw, const float* __restrict__ fb,
                     float* __restrict__ out) {
    int b = blockIdx.x >> 5, q = blockIdx.x & 31;
    __shared__ float s[64 * 64];
    int c = threadIdx.x & 63;
    int rb = threadIdx.x >> 6;
    float acc[3] = {0.f, 0.f, 0.f};
    for (int j = 0; j < 12; j++) {
        __syncthreads();
        for (int i = threadIdx.x; i < 4096; i += 256)
            s[i] = o2[((size_t)((b * 12 + j) * 2048 + q * 64)) * 64 + i] + tb2[i & 63];
        __syncthreads();
        for (int rn = 0; rn < 64; rn++) {
            float v = s[rn * 64 + c];
#pragma unroll
            for (int rr = 0; rr < 3; rr++)
                acc[rr] += v * fw[(rb * 3 + rr) * 768 + rn * 12 + j];
        }
    }
    int np = 32 * c + q;
#pragma unroll
    for (int rr = 0; rr < 3; rr++) {
        int r = rb * 3 + rr;
        out[((size_t)b * 2048 + np) * 12 + r] = acc[rr] + fb[r];
    }
}

// ---------------- host ----------------
static void* sym(const void* s) {
    void* p = nullptr;
    cudaGetSymbolAddress(&p, s);
    return p;
}

extern "C" void kernel_launch(void* const* d_in, const int* in_sizes, int n_in,
                              void* d_out, int out_size) {
    const float* x = (const float*)d_in[0];
    const int* src = (const int*)d_in[1];
    const int* dst = (const int*)d_in[2];
    const float* W1 = (const float*)d_in[3];
    const float* al1 = (const float*)d_in[4];
    const float* ar1 = (const float*)d_in[5];
    const float* b1 = (const float*)d_in[6];
    const float* W2 = (const float*)d_in[7];
    const float* al2 = (const float*)d_in[8];
    const float* ar2 = (const float*)d_in[9];
    const float* b2 = (const float*)d_in[10];
    const float* ln1w = (const float*)d_in[11];
    const float* ln1b = (const float*)d_in[12];
    const float* ln2w = (const float*)d_in[13];
    const float* ln2b = (const float*)d_in[14];
    const float* tc1w = (const float*)d_in[15];
    const float* tc1b = (const float*)d_in[16];
    const float* ln3w = (const float*)d_in[17];
    const float* ln3b = (const float*)d_in[18];
    const float* tc2w = (const float*)d_in[19];
    const float* tc2b = (const float*)d_in[20];
    const float* fcw = (const float*)d_in[21];
    const float* fcb = (const float*)d_in[22];
    int E = in_sizes[1];

    float* xT = (float*)sym(g_xT);
    float* feat = (float*)sym(g_feat);
    float* el = (float*)sym(g_el);
    float* er = (float*)sym(g_er);
    float* alpha = (float*)sym(g_alpha);
    float* y = (float*)sym(g_y);
    float* z = (float*)sym(g_z);
    float* o1 = (float*)sym(g_o1);
    float* o2 = (float*)sym(g_o2);
    float* wtm = (float*)sym(g_wtm);
    float* wp1 = (float*)sym(g_wp1);
    double* stat = (double*)sym(g_stat);
    int* deg = (int*)sym(g_deg);
    int* cursor = (int*)sym(g_cursor);
    int* rowptr = (int*)sym(g_rowptr);
    int* col = (int*)sym(g_col);
    float* out = (float*)d_out;

    // slots 1-3 setup so capture slot #4 = gemm1
    k_transpose_x<<<16384, 256>>>(x, xT, deg);                         // 1
    k_count<<<(E + 255) / 256, 256>>>(dst, deg, E);                    // 2
    k_packw128<<<32, 256>>>(W1, wp1);                                  // 3
    k_gemm8<4><<<1024, 256>>>(xT, wp1, feat, al1, ar1, el, er);        // 4 <- ncu capture
    k_scan<<<1, 1024>>>(deg, rowptr, cursor);                          // 5
    k_fill_atomic<<<(E + 255) / 256, 256>>>(dst, src, cursor, col, E); // 6
    k_sortcol<<<8, 256>>>(rowptr, col);                                // 7

    // ---- GAT layer 1 ----
    k_alpha<4><<<2048, 256>>>(el, er, rowptr, col, alpha);
    {
        dim3 g(2048, 8);
        k_gather<4><<<g, 64>>>(feat, alpha, rowptr, col, b1, y);
    }
    k_lnpart<<<256, 1024>>>(y, stat);

    // ---- GAT layer 2 (LN1 fused into wmma GEMM input) ----
    k_wgemm2t<<<1024, 256>>>(y, W2, feat, ln1w, ln1b, stat);
    k_elr2<<<16384, 256>>>(feat, al2, ar2, el, er);
    k_alpha<8><<<2048, 256>>>(el, er, rowptr, col, alpha);
    {
        dim3 g(2048, 8);
        k_gather<8><<<g, 64>>>(feat, alpha, rowptr, col, b2, z);
    }
    k_lnpart<<<512, 1024>>>(z, stat);

    // ---- output layer ----
    k_twm<<<80, 256>>>(tc1w, wtm);
    k_conv1<<<2048, 256>>>(z, wtm, tc1b, o1, ln2w, ln2b, stat);  // LN2 fused, tf32 wmma
    k_lnpart<<<384, 1024>>>(o1, stat);
    k_wgemm3t<<<1536, 256>>>(o1, tc2w, o2, ln3w, ln3b, stat);    // LN3 fused, tf32 wmma
    k_fc<<<256, 256>>>(o2, tc2b, fcw, fcb, out);
}